// round 13
// baseline (speedup 1.0000x reference)
#include <cuda_runtime.h>
#include <cuda_bf16.h>
#include <math.h>
#include <stdint.h>

// Problem constants
#define B_  2
#define T_  1024
#define S_  2048
#define D_  1024
#define H_  16
#define HD_ 64
#define SCALE_ 0.125f
#define RMS_EPS_ 1e-6f

#define NS_ 2
#define SPS (S_ / NS_)

// bf16-split GEMM config
#define KTOT (3 * D_)
#define KB2 64                    // bf16 K per stage
#define NITER2 (KTOT / KB2)       // 48
#define GTN 128
#define GPITCH 144                // smem row pitch bytes
#define WSTAGE (128 * GPITCH)     // W stage bytes

// attention mma config
#define AM 128
#define AKE 192
#define APB 400
#define ATTN_SMEM ((AM + 64 + 64) * APB)  // 102400

// Scratch (device globals; no allocation allowed)
__device__ float g_v[B_ * S_ * D_];
__device__ float g_proj[B_ * T_ * D_];
__device__ float g_pacc[NS_ * B_ * H_ * T_ * HD_];
__device__ float g_pm[NS_ * B_ * H_ * T_];
__device__ float g_pl[NS_ * B_ * H_ * T_];
__device__ __nv_bfloat16 g_qs[(size_t)B_ * T_ * KTOT];
__device__ __nv_bfloat16 g_cs[(size_t)B_ * S_ * KTOT];
__device__ __nv_bfloat16 g_as[(size_t)B_ * T_ * KTOT];
__device__ __nv_bfloat16 g_wqs[(size_t)D_ * KTOT];
__device__ __nv_bfloat16 g_wks[(size_t)D_ * KTOT];
__device__ __nv_bfloat16 g_wvs[(size_t)D_ * KTOT];
__device__ __nv_bfloat16 g_wos[(size_t)D_ * KTOT];
__device__ __nv_bfloat16 g_qe[(size_t)B_ * H_ * T_ * AKE];
__device__ __nv_bfloat16 g_ke[(size_t)B_ * H_ * S_ * AKE];
__device__ __nv_bfloat16 g_vte[(size_t)B_ * H_ * HD_ * 2 * S_];

// ============================ PTX helpers (base ISA) ========================
__device__ __forceinline__ uint32_t smem_u32(const void* p) {
    uint32_t a;
    asm("{ .reg .u64 t; cvta.to.shared.u64 t, %1; cvt.u32.u64 %0, t; }"
        : "=r"(a) : "l"(p));
    return a;
}

#define CP_ASYNC16(dst_u32, src_ptr) \
    asm volatile("cp.async.cg.shared.global [%0], [%1], 16;" \
        :: "r"(dst_u32), "l"(src_ptr))
#define CP_COMMIT() asm volatile("cp.async.commit_group;" ::: "memory")
#define CP_WAIT2()  asm volatile("cp.async.wait_group 2;" ::: "memory")
#define CP_WAIT0()  asm volatile("cp.async.wait_group 0;" ::: "memory")

#define LDMATRIX_X4(r0, r1, r2, r3, addr) \
    asm volatile("ldmatrix.sync.aligned.m8n8.x4.shared.b16 {%0,%1,%2,%3}, [%4];" \
        : "=r"(r0), "=r"(r1), "=r"(r2), "=r"(r3) : "r"(addr))

#define MMA16816(d0, d1, d2, d3, a0, a1, a2, a3, b0, b1) \
    asm volatile("mma.sync.aligned.m16n8k16.row.col.f32.bf16.bf16.f32 " \
        "{%0,%1,%2,%3}, {%4,%5,%6,%7}, {%8,%9}, {%0,%1,%2,%3};" \
        : "+f"(d0), "+f"(d1), "+f"(d2), "+f"(d3) \
        : "r"(a0), "r"(a1), "r"(a2), "r"(a3), "r"(b0), "r"(b1))

__device__ __forceinline__ uint32_t pack_bf16x2(float p0, float p1) {
    uint32_t d;
    asm("cvt.rn.bf16x2.f32 %0, %1, %2;" : "=r"(d) : "f"(p1), "f"(p0));
    return d;
}
__device__ __forceinline__ float bf16lo_f(uint32_t u) {
    return __uint_as_float(u << 16);
}
__device__ __forceinline__ float bf16hi_f(uint32_t u) {
    return __uint_as_float(u & 0xffff0000u);
}

// ---------------------------------------------------------------------------
// Mega split kernel (unchanged).
// ---------------------------------------------------------------------------
__global__ __launch_bounds__(256) void split_all(
    const float* __restrict__ query, const float* __restrict__ context,
    const float* __restrict__ Wq, const float* __restrict__ Wk,
    const float* __restrict__ Wv, const float* __restrict__ Wo)
{
    const int bid = blockIdx.x;
    const float* in;
    __nv_bfloat16* out;
    int act;
    if (bid < 2048) {
        in = query + (size_t)bid * D_;
        out = g_qs + (size_t)bid * KTOT;
        act = 1;
    } else if (bid < 6144) {
        int r = bid - 2048;
        in = context + (size_t)r * D_;
        out = g_cs + (size_t)r * KTOT;
        act = 1;
    } else {
        int idx = bid - 6144;
        int w = idx >> 10;
        int r = idx & 1023;
        const float* Ws[4] = {Wq, Wk, Wv, Wo};
        __nv_bfloat16* Os[4];
        Os[0] = g_wqs; Os[1] = g_wks; Os[2] = g_wvs; Os[3] = g_wos;
        in = Ws[w] + (size_t)r * D_;
        out = Os[w] + (size_t)r * KTOT;
        act = 0;
    }
    #pragma unroll
    for (int i = 0; i < 4; i++) {
        int c = threadIdx.x + i * 256;
        float x = in[c];
        __nv_bfloat16 hi = __float2bfloat16(x);
        __nv_bfloat16 lo = __float2bfloat16(x - __bfloat162float(hi));
        if (act) { out[c] = hi; out[D_ + c] = hi; out[2 * D_ + c] = lo; }
        else     { out[c] = hi; out[D_ + c] = lo; out[2 * D_ + c] = hi; }
    }
}

// v_ext_t (unchanged)
__global__ __launch_bounds__(256) void v_ext_t(
    const float* __restrict__ v, __nv_bfloat16* __restrict__ out)
{
    __shared__ float tile[32][33];
    const int s0 = blockIdx.x * 32;
    const int d0 = blockIdx.y * 32;
    const int bh = blockIdx.z;
    const int b = bh / H_;
    const int h = bh % H_;
    const int tx = threadIdx.x, ty = threadIdx.y;
    #pragma unroll
    for (int i = 0; i < 4; i++) {
        int s = s0 + ty + i * 8;
        tile[ty + i * 8][tx] = v[((size_t)(b * S_ + s)) * D_ + h * 64 + d0 + tx];
    }
    __syncthreads();
    #pragma unroll
    for (int i = 0; i < 4; i++) {
        int d = d0 + ty + i * 8;
        float x = tile[tx][ty + i * 8];
        __nv_bfloat16 hi = __float2bfloat16(x);
        __nv_bfloat16 lo = __float2bfloat16(x - __bfloat162float(hi));
        __nv_bfloat16* orow = out + ((size_t)(bh * 64 + d)) * (2 * S_);
        orow[s0 + tx] = hi;
        orow[S_ + s0 + tx] = lo;
    }
}

// ---------------------------------------------------------------------------
// bf16 mma.sync GEMM, 512 threads (16 warps, 4M x 4N grid).
// Tile (64*MB) x 128, warp tile (16*MB) x 32. 4-buffer cp.async ring.
// emode 0: C fp32. emode 1: qe ext [hi|hi|lo]. emode 2: ke ext [hi|lo|hi].
// ---------------------------------------------------------------------------
template <int MB>
__global__ __launch_bounds__(512, 1) void gemm_bf16_mma(
    const __nv_bfloat16* __restrict__ A, const __nv_bfloat16* __restrict__ W,
    float* __restrict__ C, __nv_bfloat16* __restrict__ eout,
    int N, int emode, int Lrows)
{
    constexpr int BM = 64 * MB;
    constexpr int ASTAGE = BM * GPITCH;
    constexpr int STAGE = ASTAGE + WSTAGE;

    extern __shared__ char gsm[];
    const uint32_t smb = smem_u32(gsm);

    const int tid = threadIdx.x;
    const int wid = tid >> 5;
    const int lane = tid & 31;
    const int wm = wid & 3;            // 4 M-warps
    const int wn = wid >> 2;           // 4 N-warps
    const int bm = blockIdx.y * BM;
    const int bn = blockIdx.x * GTN;

    // loader mappings (512 threads)
    constexpr int A_TPR = 512 / BM;            // threads per A row (2 or 4)
    constexpr int A_CH = 8 / A_TPR;            // 16B chunks per thread (4 or 2)
    const int a_lrow = tid / A_TPR;
    const int a_sub = tid % A_TPR;
    const int w_lrow = tid >> 2;               // W: 128 rows, 4 thr/row
    const int w_sub = tid & 3;                 // 2 chunks each

    const __nv_bfloat16* Ag = A + (size_t)(bm + a_lrow) * KTOT + a_sub * (A_CH * 8);
    const __nv_bfloat16* Wg = W + (size_t)(bn + w_lrow) * KTOT + w_sub * 16;
    const uint32_t a_lsm = a_lrow * GPITCH + a_sub * (A_CH * 16);
    const uint32_t w_lsm = w_lrow * GPITCH + w_sub * 32;

    float acc[MB][4][4];
    #pragma unroll
    for (int mb = 0; mb < MB; mb++)
        #pragma unroll
        for (int nb = 0; nb < 4; nb++)
            #pragma unroll
            for (int i = 0; i < 4; i++) acc[mb][nb][i] = 0.f;

    const uint32_t a_row = wm * (16 * MB) + (lane & 15);
    const uint32_t a_koff = (lane >> 4) * 16;
    const uint32_t b_row = wn * 32 + (lane & 7) + 8 * ((lane >> 4) & 1);
    const uint32_t b_koff = ((lane >> 3) & 1) * 16;

    // prologue: stages 0,1,2
    #pragma unroll
    for (int st = 0; st < 3; st++) {
        const uint32_t ab = smb + st * STAGE;
        #pragma unroll
        for (int j = 0; j < A_CH; j++)
            CP_ASYNC16(ab + a_lsm + j * 16, Ag + st * KB2 + j * 8);
        #pragma unroll
        for (int j = 0; j < 2; j++)
            CP_ASYNC16(ab + ASTAGE + w_lsm + j * 16, Wg + st * KB2 + j * 8);
        CP_COMMIT();
    }

    for (int c = 0; c < NITER2; c++) {
        const int buf = c & 3;
        CP_WAIT2();
        __syncthreads();

        if (c + 3 < NITER2) {
            const uint32_t pb = smb + ((c + 3) & 3) * STAGE;
            #pragma unroll
            for (int j = 0; j < A_CH; j++)
                CP_ASYNC16(pb + a_lsm + j * 16, Ag + (c + 3) * KB2 + j * 8);
            #pragma unroll
            for (int j = 0; j < 2; j++)
                CP_ASYNC16(pb + ASTAGE + w_lsm + j * 16, Wg + (c + 3) * KB2 + j * 8);
        }
        CP_COMMIT();

        const uint32_t ab = smb + buf * STAGE;
        const uint32_t bb = ab + ASTAGE;

        #pragma unroll
        for (int kk = 0; kk < 4; kk++) {
            uint32_t aF[MB][4], bF[4][2];
            #pragma unroll
            for (int mb = 0; mb < MB; mb++) {
                uint32_t addr = ab + (a_row + mb * 16) * GPITCH + kk * 32 + a_koff;
                LDMATRIX_X4(aF[mb][0], aF[mb][1], aF[mb][2], aF[mb][3], addr);
            }
            #pragma unroll
            for (int nb2 = 0; nb2 < 2; nb2++) {
                uint32_t addr = bb + (b_row + nb2 * 16) * GPITCH + kk * 32 + b_koff;
                LDMATRIX_X4(bF[nb2 * 2][0], bF[nb2 * 2][1],
                            bF[nb2 * 2 + 1][0], bF[nb2 * 2 + 1][1], addr);
            }
            #pragma unroll
            for (int mb = 0; mb < MB; mb++)
                #pragma unroll
                for (int nb = 0; nb < 4; nb++)
                    MMA16816(acc[mb][nb][0], acc[mb][nb][1],
                             acc[mb][nb][2], acc[mb][nb][3],
                             aF[mb][0], aF[mb][1], aF[mb][2], aF[mb][3],
                             bF[nb][0], bF[nb][1]);
        }
    }
    CP_WAIT0();

    const int gr = lane >> 2;
    const int gc = (lane & 3) * 2;

    if (emode == 0) {
        #pragma unroll
        for (int mb = 0; mb < MB; mb++) {
            const int row0 = bm + wm * (16 * MB) + mb * 16 + gr;
            #pragma unroll
            for (int nb = 0; nb < 4; nb++) {
                const int col = bn + wn * 32 + nb * 8 + gc;
                *(float2*)&C[(size_t)row0 * N + col] =
                    make_float2(acc[mb][nb][0], acc[mb][nb][1]);
                *(float2*)&C[(size_t)(row0 + 8) * N + col] =
                    make_float2(acc[mb][nb][2], acc[mb][nb][3]);
            }
        }
    } else {
        #pragma unroll
        for (int mb = 0; mb < MB; mb++) {
            #pragma unroll
            for (int half = 0; half < 2; half++) {
                const int row = bm + wm * (16 * MB) + mb * 16 + gr + half * 8;
                const int b = row / Lrows;
                const int t = row % Lrows;
                #pragma unroll
                for (int nb = 0; nb < 4; nb++) {
                    const int col = bn + wn * 32 + nb * 8 + gc;
                    const int h = col >> 6;
                    const int dd = col & 63;
                    float x0 = acc[mb][nb][half * 2];
                    float x1 = acc[mb][nb][half * 2 + 1];
                    __nv_bfloat16 h0 = __float2bfloat16(x0);
                    __nv_bfloat16 h1 = __float2bfloat16(x1);
                    __nv_bfloat16 l0 = __float2bfloat16(x0 - __bfloat162float(h0));
                    __nv_bfloat16 l1 = __float2bfloat16(x1 - __bfloat162float(h1));
                    __nv_bfloat16* orow =
                        eout + ((size_t)(b * H_ + h) * Lrows + t) * AKE;
                    __nv_bfloat162 hv; hv.x = h0; hv.y = h1;
                    __nv_bfloat162 lv; lv.x = l0; lv.y = l1;
                    if (emode == 1) {
                        *(__nv_bfloat162*)&orow[dd] = hv;
                        *(__nv_bfloat162*)&orow[64 + dd] = hv;
                        *(__nv_bfloat162*)&orow[128 + dd] = lv;
                    } else {
                        *(__nv_bfloat162*)&orow[dd] = hv;
                        *(__nv_bfloat162*)&orow[64 + dd] = lv;
                        *(__nv_bfloat162*)&orow[128 + dd] = hv;
                    }
                }
            }
        }
    }
}

// ---------------------------------------------------------------------------
// Tensor-core flash attention (unchanged, validated).
// ---------------------------------------------------------------------------
__global__ __launch_bounds__(256) void attn_mma(
    const __nv_bfloat16* __restrict__ qe,
    const __nv_bfloat16* __restrict__ ke,
    const __nv_bfloat16* __restrict__ vte)
{
    extern __shared__ char smraw[];
    const uint32_t sQ = smem_u32(smraw);
    const uint32_t sK = sQ + AM * APB;
    const uint32_t sV = sK + 64 * APB;

    const int tid = threadIdx.x;
    const int wid = tid >> 5;
    const int lane = tid & 31;
    const int hb = blockIdx.z;
    const int split = blockIdx.y;
    const int t0 = blockIdx.x * AM;
    const int h = hb % H_;

    const float slope = exp2f(-(float)(h + 1) / 16.0f);
    const size_t qrow0 = (size_t)hb * T_ + t0;
    const size_t krow0 = (size_t)hb * S_;
    const size_t vrow0 = (size_t)hb * 64;

    for (int idx = tid; idx < AM * 24; idx += 256) {
        int r = idx / 24, c = idx % 24;
        CP_ASYNC16(sQ + r * APB + c * 16, qe + (qrow0 + r) * AKE + c * 8);
    }
    CP_COMMIT();

    float sc[8][4], oF[8][4];
    #pragma unroll
    for (int nb = 0; nb < 8; nb++)
        #pragma unroll
        for (int i = 0; i < 4; i++) oF[nb][i] = 0.f;
    float m0 = -INFINITY, m1 = -INFINITY, l0 = 0.f, l1 = 0.f;

    const int r0 = lane >> 2;
    const float trow0 = (float)(t0 + wid * 16 + r0);
    const float trow1 = trow0 + 8.0f;

    const uint32_t a_addr_base = sQ + (wid * 16 + (lane & 15)) * APB + (lane >> 4) * 16;
    const uint32_t b_row = (lane & 7) + 8 * ((lane >> 4) & 1);
    const uint32_t b_koff = ((lane >> 3) & 1) * 16;

    const int sbeg = split * SPS;
    const int send = sbeg + SPS;

    for (int s0 = sbeg; s0 < send; s0 += 64) {
        for (int idx = tid; idx < 64 * 24; idx += 256) {
            int r = idx / 24, c = idx % 24;
            CP_ASYNC16(sK + r * APB + c * 16, ke + (krow0 + s0 + r) * AKE + c * 8);
        }
        for (int idx = tid; idx < 64 * 24; idx += 256) {
            int r = idx / 24, c = idx % 24;
            const __nv_bfloat16* vb = vte + (vrow0 + r) * (size_t)(2 * S_);
            const __nv_bfloat16* src =
                (c < 8) ? vb + s0 + c * 8
                        : (c < 16 ? vb + S_ + s0 + (c - 8) * 8
                                  : vb + s0 + (c - 16) * 8);
            CP_ASYNC16(sV + r * APB + c * 16, src);
        }
        CP_COMMIT();
        CP_WAIT0();
        __syncthreads();

        #pragma unroll
        for (int nb = 0; nb < 8; nb++)
            #pragma unroll
            for (int i = 0; i < 4; i++) sc[nb][i] = 0.f;

        #pragma unroll
        for (int ks = 0; ks < 12; ks++) {
            uint32_t aF[4], bF[8][2];
            LDMATRIX_X4(aF[0], aF[1], aF[2], aF[3], a_addr_base + ks * 32);
            #pragma unroll
            for (int nb2 = 0; nb2 < 4; nb2++) {
                uint32_t addr = sK + (b_row + nb2 * 16) * APB + ks * 32 + b_koff;
                LDMATRIX_X4(bF[nb2 * 2][0], bF[nb2 * 2][1],
                            bF[nb2 * 2 + 1][0], bF[nb2 * 2 + 1][1], addr);
            }
            #pragma unroll
            for (int nb = 0; nb < 8; nb++)
                MMA16816(sc[nb][0], sc[nb][1], sc[nb][2], sc[nb][3],
                         aF[0], aF[1], aF[2], aF[3], bF[nb][0], bF[nb][1]);
        }

        float tm0 = -INFINITY, tm1 = -INFINITY;
        #pragma unroll
        for (int nb = 0; nb < 8; nb++) {
            float scol = (float)(s0 + nb * 8 + 2 * (lane & 3));
            sc[nb][0] = sc[nb][0] * SCALE_ - slope * fabsf(trow0 - scol);
            sc[nb][1] = sc[nb][1] * SCALE_ - slope * fabsf(trow0 - (scol + 1.f));
            sc[nb][2] = sc[nb][2] * SCALE_ - slope * fabsf(trow1 - scol);
            sc[nb][3] = sc[nb][3] * SCALE_ - slope * fabsf(trow1 - (scol + 1.f));
            tm0 = fmaxf(tm0, fmaxf(sc[nb][0], sc[nb][1]));
            tm1 = fmaxf(tm1, fmaxf(sc[nb][2], sc[nb][3]));
        }
        tm0 = fmaxf(tm0, __shfl_xor_sync(0xffffffffu, tm0, 1));
        tm0 = fmaxf(tm0, __shfl_xor_sync(0xffffffffu, tm0, 2));
        tm1 = fmaxf(tm1, __shfl_xor_sync(0xffffffffu, tm1, 1));
        tm1 = fmaxf(tm1, __shfl_xor_sync(0xffffffffu, tm1, 2));

        float mn0 = fmaxf(m0, tm0);
        float mn1 = fmaxf(m1, tm1);
        float cr0 = __expf(m0 - mn0);
        float cr1 = __expf(m1 - mn1);
        l0 *= cr0; l1 *= cr1;
        #pragma unroll
        for (int nb = 0; nb < 8; nb++) {
            oF[nb][0] *= cr0; oF[nb][1] *= cr0;
            oF[nb][2] *= cr1; oF[nb][3] *= cr1;
        }

        float rs0 = 0.f, rs1 = 0.f;
        #pragma unroll
        for (int nb = 0; nb < 8; nb++) {
            sc[nb][0] = __expf(sc[nb][0] - mn0);
            sc[nb][1] = __expf(sc[nb][1] - mn0);
            sc[nb][2] = __expf(sc[nb][2] - mn1);
            sc[nb][3] = __expf(sc[nb][3] - mn1);
            rs0 += sc[nb][0] + sc[nb][1];
            rs1 += sc[nb][2] + sc[nb][3];
        }
        rs0 += __shfl_xor_sync(0xffffffffu, rs0, 1);
        rs0 += __shfl_xor_sync(0xffffffffu, rs0, 2);
        rs1 += __shfl_xor_sync(0xffffffffu, rs1, 1);
        rs1 += __shfl_xor_sync(0xffffffffu, rs1, 2);
        l0 += rs0; l1 += rs1;
        m0 = mn0; m1 = mn1;

        uint32_t phi[4][4];
        #pragma unroll
        for (int ks = 0; ks < 4; ks++) {
            phi[ks][0] = pack_bf16x2(sc[2 * ks][0], sc[2 * ks][1]);
            phi[ks][1] = pack_bf16x2(sc[2 * ks][2], sc[2 * ks][3]);
            phi[ks][2] = pack_bf16x2(sc[2 * ks + 1][0], sc[2 * ks + 1][1]);
            phi[ks][3] = pack_bf16x2(sc[2 * ks + 1][2], sc[2 * ks + 1][3]);
        }

        #pragma unroll
        for (int ks = 0; ks < 12; ks++) {
            uint32_t bF[8][2];
            #pragma unroll
            for (int nb2 = 0; nb2 < 4; nb2++) {
                uint32_t addr = sV + (b_row + nb2 * 16) * APB + ks * 32 + b_koff;
                LDMATRIX_X4(bF[nb2 * 2][0], bF[nb2 * 2][1],
                            bF[nb2 * 2 + 1][0], bF[nb2 * 2 + 1][1], addr);
            }
            uint32_t aP[4];
            if (ks < 8) {
                const int kk = ks & 3;
                aP[0] = phi[kk][0]; aP[1] = phi[kk][1];
                aP[2] = phi[kk][2]; aP[3] = phi[kk][3];
            } else {
                const int kk = ks - 8;
                #pragma unroll
                for (int j = 0; j < 4; j++) {
                    const int nb = 2 * kk + (j >> 1);
                    const int ci = (j & 1) * 2;
                    float pe = sc[nb][ci]     - bf16lo_f(phi[kk][j]);
                    float po = sc[nb][ci + 1] - bf16hi_f(phi[kk][j]);
                    aP[j] = pack_bf16x2(pe, po);
                }
            }
            #pragma unroll
            for (int nb = 0; nb < 8; nb++)
                MMA16816(oF[nb][0], oF[nb][1], oF[nb][2], oF[nb][3],
                         aP[0], aP[1], aP[2], aP[3], bF[nb][0], bF[nb][1]);
        }
        __syncthreads();
    }

    const size_t base = (size_t)(split * B_ * H_ + hb) * T_;
    const size_t pidx0 = base + t0 + wid * 16 + r0;
    const size_t pidx1 = pidx0 + 8;
    #pragma unroll
    for (int nb = 0; nb < 8; nb++) {
        const int col = nb * 8 + 2 * (lane & 3);
        *(float2*)&g_pacc[pidx0 * HD_ + col] = make_float2(oF[nb][0], oF[nb][1]);
        *(float2*)&g_pacc[pidx1 * HD_ + col] = make_float2(oF[nb][2], oF[nb][3]);
    }
    if ((lane & 3) == 0) {
        g_pm[pidx0] = m0; g_pl[pidx0] = l0;
        g_pm[pidx1] = m1; g_pl[pidx1] = l1;
    }
}

// ---------------------------------------------------------------------------
// Combine split-KV partials -> split-act layout (unchanged)
// ---------------------------------------------------------------------------
__global__ __launch_bounds__(256) void attn_combine_kernel(
    __nv_bfloat16* __restrict__ as_out)
{
    const int d = threadIdx.x & 63;
    const int rlocal = threadIdx.x >> 6;
    const size_t row = (size_t)blockIdx.x * 4 + rlocal;
    const int t = row % T_;
    const int h = (row / T_) % H_;
    const int b = row / ((size_t)T_ * H_);

    float m0 = g_pm[row];
    float l0 = g_pl[row];
    float m1 = g_pm[(size_t)B_ * H_ * T_ + row];
    float l1 = g_pl[(size_t)B_ * H_ * T_ + row];

    float M = fmaxf(m0, m1);
    float e0 = __expf(m0 - M), e1 = __expf(m1 - M);
    float L = l0 * e0 + l1 * e1;
    float inv = 1.f / L;

    float a0 = g_pacc[row * HD_ + d];
    float a1 = g_pacc[((size_t)B_ * H_ * T_ + row) * HD_ + d];
    float val = (a0 * e0 + a1 * e1) * inv;

    __nv_bfloat16 hi = __float2bfloat16(val);
    __nv_bfloat16 lo = __float2bfloat16(val - __bfloat162float(hi));
    const int c = h * 64 + d;
    __nv_bfloat16* orow = as_out + ((size_t)(b * T_ + t)) * KTOT;
    orow[c] = hi; orow[D_ + c] = hi; orow[2 * D_ + c] = lo;
}

// ---------------------------------------------------------------------------
// residual + RMSNorm (unchanged)
// ---------------------------------------------------------------------------
__global__ __launch_bounds__(256) void rms_kernel(
    const float* __restrict__ query, const float* __restrict__ proj,
    const float* __restrict__ w, float* __restrict__ out)
{
    __shared__ float sh[8];
    __shared__ float s_inv;
    const size_t row = blockIdx.x;
    const float* qr = query + row * D_;
    const float* pr = proj + row * D_;
    float* orow = out + row * D_;

    float x[4];
    float ss = 0.f;
    #pragma unroll
    for (int i = 0; i < 4; i++) {
        int idx = threadIdx.x + i * 256;
        x[i] = qr[idx] + pr[idx];
        ss += x[i] * x[i];
    }
    #pragma unroll
    for (int ofs = 16; ofs > 0; ofs >>= 1)
        ss += __shfl_xor_sync(0xffffffffu, ss, ofs);
    const int lane = threadIdx.x & 31, wid = threadIdx.x >> 5;
    if (lane == 0) sh[wid] = ss;
    __syncthreads();
    if (threadIdx.x == 0) {
        float tot = 0.f;
        #pragma unroll
        for (int i = 0; i < 8; i++) tot += sh[i];
        s_inv = rsqrtf(tot * (1.0f / D_) + RMS_EPS_);
    }
    __syncthreads();
    const float inv = s_inv;
    #pragma unroll
    for (int i = 0; i < 4; i++) {
        int idx = threadIdx.x + i * 256;
        orow[idx] = x[i] * inv * w[idx];
    }
}

// ---------------------------------------------------------------------------
extern "C" void kernel_launch(void* const* d_in, const int* in_sizes, int n_in,
                              void* d_out, int out_size)
{
    const float* query   = (const float*)d_in[0];
    const float* context = (const float*)d_in[1];
    const float* Wq      = (const float*)d_in[2];
    const float* Wk      = (const float*)d_in[3];
    const float* Wv      = (const float*)d_in[4];
    const float* Wo      = (const float*)d_in[5];
    const float* rmsw    = (const float*)d_in[6];
    float* out = (float*)d_out;

    float *pv, *pproj;
    cudaGetSymbolAddress((void**)&pv,    g_v);
    cudaGetSymbolAddress((void**)&pproj, g_proj);

    __nv_bfloat16 *qs, *cs, *as, *wqs, *wks, *wvs, *wos, *qe, *kke, *vte;
    cudaGetSymbolAddress((void**)&qs,  g_qs);
    cudaGetSymbolAddress((void**)&cs,  g_cs);
    cudaGetSymbolAddress((void**)&as,  g_as);
    cudaGetSymbolAddress((void**)&wqs, g_wqs);
    cudaGetSymbolAddress((void**)&wks, g_wks);
    cudaGetSymbolAddress((void**)&wvs, g_wvs);
    cudaGetSymbolAddress((void**)&wos, g_wos);
    cudaGetSymbolAddress((void**)&qe,  g_qe);
    cudaGetSymbolAddress((void**)&kke, g_ke);
    cudaGetSymbolAddress((void**)&vte, g_vte);

    const int SM2 = 4 * (128 * GPITCH + WSTAGE);   // 147456
    const int SM4 = 4 * (256 * GPITCH + WSTAGE);   // 221184
    cudaFuncSetAttribute(gemm_bf16_mma<2>,
        cudaFuncAttributeMaxDynamicSharedMemorySize, SM2);
    cudaFuncSetAttribute(gemm_bf16_mma<4>,
        cudaFuncAttributeMaxDynamicSharedMemorySize, SM4);
    cudaFuncSetAttribute(attn_mma,
        cudaFuncAttributeMaxDynamicSharedMemorySize, ATTN_SMEM);

    const int MQ = B_ * T_;   // 2048
    const int MK = B_ * S_;   // 4096

    // all input conversions in one launch
    split_all<<<10240, 256>>>(query, context, Wq, Wk, Wv, Wo);

    // projections (512-thread CTAs)
    dim3 gq(D_ / GTN, MQ / 128);    // MB=2
    dim3 gk(D_ / GTN, MK / 256);    // MB=4
    gemm_bf16_mma<2><<<gq, 512, SM2>>>(qs, wqs, nullptr, qe,  D_, 1, T_);
    gemm_bf16_mma<4><<<gk, 512, SM4>>>(cs, wks, nullptr, kke, D_, 2, S_);
    gemm_bf16_mma<4><<<gk, 512, SM4>>>(cs, wvs, pv, nullptr,  D_, 0, 0);

    v_ext_t<<<dim3(S_ / 32, 2, B_ * H_), dim3(32, 8)>>>(pv, vte);

    // tensor-core attention
    attn_mma<<<dim3(T_ / AM, NS_, B_ * H_), 256, ATTN_SMEM>>>(qe, kke, vte);
    attn_combine_kernel<<<(B_ * H_ * T_) / 4, 256>>>(as);

    // output projection
    gemm_bf16_mma<2><<<gq, 512, SM2>>>(as, wos, pproj, nullptr, D_, 0, 0);

    rms_kernel<<<MQ, 256>>>(query, pproj, rmsw, out);
}

// round 14
// speedup vs baseline: 1.3539x; 1.3539x over previous
#include <cuda_runtime.h>
#include <cuda_bf16.h>
#include <math.h>
#include <stdint.h>

// Problem constants
#define B_  2
#define T_  1024
#define S_  2048
#define D_  1024
#define H_  16
#define HD_ 64
#define SCALE_ 0.125f
#define RMS_EPS_ 1e-6f

#define NS_ 2
#define SPS (S_ / NS_)

// bf16-split GEMM config
#define KTOT (3 * D_)
#define KB2 64                    // bf16 K per stage
#define NITER2 (KTOT / KB2)       // 48
#define GTM 128
#define GTN 128
#define GPITCH 144                // smem row pitch bytes
#define ASTAGE (GTM * GPITCH)     // 18432
#define STAGE (2 * ASTAGE)        // A + W per stage = 36864
#define GEMM_SMEM (2 * STAGE)     // 2 stages = 73728 (2 CTAs/SM)

// attention mma config
#define AM 128
#define AKE 192
#define APB 400
#define ATTN_SMEM ((AM + 64 + 64) * APB)  // 102400

// Scratch (device globals; no allocation allowed)
__device__ float g_v[B_ * S_ * D_];
__device__ float g_proj[B_ * T_ * D_];
__device__ float g_pacc[NS_ * B_ * H_ * T_ * HD_];
__device__ float g_pm[NS_ * B_ * H_ * T_];
__device__ float g_pl[NS_ * B_ * H_ * T_];
__device__ __nv_bfloat16 g_qs[(size_t)B_ * T_ * KTOT];
__device__ __nv_bfloat16 g_cs[(size_t)B_ * S_ * KTOT];
__device__ __nv_bfloat16 g_as[(size_t)B_ * T_ * KTOT];
__device__ __nv_bfloat16 g_wqs[(size_t)D_ * KTOT];
__device__ __nv_bfloat16 g_wks[(size_t)D_ * KTOT];
__device__ __nv_bfloat16 g_wvs[(size_t)D_ * KTOT];
__device__ __nv_bfloat16 g_wos[(size_t)D_ * KTOT];
__device__ __nv_bfloat16 g_qe[(size_t)B_ * H_ * T_ * AKE];
__device__ __nv_bfloat16 g_ke[(size_t)B_ * H_ * S_ * AKE];
__device__ __nv_bfloat16 g_vte[(size_t)B_ * H_ * HD_ * 2 * S_];

// ============================ PTX helpers (base ISA) ========================
__device__ __forceinline__ uint32_t smem_u32(const void* p) {
    uint32_t a;
    asm("{ .reg .u64 t; cvta.to.shared.u64 t, %1; cvt.u32.u64 %0, t; }"
        : "=r"(a) : "l"(p));
    return a;
}

#define CP_ASYNC16(dst_u32, src_ptr) \
    asm volatile("cp.async.cg.shared.global [%0], [%1], 16;" \
        :: "r"(dst_u32), "l"(src_ptr))
#define CP_COMMIT() asm volatile("cp.async.commit_group;" ::: "memory")
#define CP_WAIT1()  asm volatile("cp.async.wait_group 1;" ::: "memory")
#define CP_WAIT0()  asm volatile("cp.async.wait_group 0;" ::: "memory")

#define LDMATRIX_X4(r0, r1, r2, r3, addr) \
    asm volatile("ldmatrix.sync.aligned.m8n8.x4.shared.b16 {%0,%1,%2,%3}, [%4];" \
        : "=r"(r0), "=r"(r1), "=r"(r2), "=r"(r3) : "r"(addr))

#define MMA16816(d0, d1, d2, d3, a0, a1, a2, a3, b0, b1) \
    asm volatile("mma.sync.aligned.m16n8k16.row.col.f32.bf16.bf16.f32 " \
        "{%0,%1,%2,%3}, {%4,%5,%6,%7}, {%8,%9}, {%0,%1,%2,%3};" \
        : "+f"(d0), "+f"(d1), "+f"(d2), "+f"(d3) \
        : "r"(a0), "r"(a1), "r"(a2), "r"(a3), "r"(b0), "r"(b1))

__device__ __forceinline__ uint32_t pack_bf16x2(float p0, float p1) {
    uint32_t d;
    asm("cvt.rn.bf16x2.f32 %0, %1, %2;" : "=r"(d) : "f"(p1), "f"(p0));
    return d;
}
__device__ __forceinline__ float bf16lo_f(uint32_t u) {
    return __uint_as_float(u << 16);
}
__device__ __forceinline__ float bf16hi_f(uint32_t u) {
    return __uint_as_float(u & 0xffff0000u);
}

// ---------------------------------------------------------------------------
// Mega split kernel (unchanged, validated).
// ---------------------------------------------------------------------------
__global__ __launch_bounds__(256) void split_all(
    const float* __restrict__ query, const float* __restrict__ context,
    const float* __restrict__ Wq, const float* __restrict__ Wk,
    const float* __restrict__ Wv, const float* __restrict__ Wo)
{
    const int bid = blockIdx.x;
    const float* in;
    __nv_bfloat16* out;
    int act;
    if (bid < 2048) {
        in = query + (size_t)bid * D_;
        out = g_qs + (size_t)bid * KTOT;
        act = 1;
    } else if (bid < 6144) {
        int r = bid - 2048;
        in = context + (size_t)r * D_;
        out = g_cs + (size_t)r * KTOT;
        act = 1;
    } else {
        int idx = bid - 6144;
        int w = idx >> 10;
        int r = idx & 1023;
        const float* Ws[4] = {Wq, Wk, Wv, Wo};
        __nv_bfloat16* Os[4];
        Os[0] = g_wqs; Os[1] = g_wks; Os[2] = g_wvs; Os[3] = g_wos;
        in = Ws[w] + (size_t)r * D_;
        out = Os[w] + (size_t)r * KTOT;
        act = 0;
    }
    #pragma unroll
    for (int i = 0; i < 4; i++) {
        int c = threadIdx.x + i * 256;
        float x = in[c];
        __nv_bfloat16 hi = __float2bfloat16(x);
        __nv_bfloat16 lo = __float2bfloat16(x - __bfloat162float(hi));
        if (act) { out[c] = hi; out[D_ + c] = hi; out[2 * D_ + c] = lo; }
        else     { out[c] = hi; out[D_ + c] = lo; out[2 * D_ + c] = hi; }
    }
}

// v_ext_t (unchanged, validated)
__global__ __launch_bounds__(256) void v_ext_t(
    const float* __restrict__ v, __nv_bfloat16* __restrict__ out)
{
    __shared__ float tile[32][33];
    const int s0 = blockIdx.x * 32;
    const int d0 = blockIdx.y * 32;
    const int bh = blockIdx.z;
    const int b = bh / H_;
    const int h = bh % H_;
    const int tx = threadIdx.x, ty = threadIdx.y;
    #pragma unroll
    for (int i = 0; i < 4; i++) {
        int s = s0 + ty + i * 8;
        tile[ty + i * 8][tx] = v[((size_t)(b * S_ + s)) * D_ + h * 64 + d0 + tx];
    }
    __syncthreads();
    #pragma unroll
    for (int i = 0; i < 4; i++) {
        int d = d0 + ty + i * 8;
        float x = tile[tx][ty + i * 8];
        __nv_bfloat16 hi = __float2bfloat16(x);
        __nv_bfloat16 lo = __float2bfloat16(x - __bfloat162float(hi));
        __nv_bfloat16* orow = out + ((size_t)(bh * 64 + d)) * (2 * S_);
        orow[s0 + tx] = hi;
        orow[S_ + s0 + tx] = hi;     // placeholder, fixed next line
        orow[S_ + s0 + tx] = lo;
    }
}

// ---------------------------------------------------------------------------
// bf16 mma.sync GEMM: 128x128 tile, 256 threads (8 warps, 4M x 2N),
// 2-stage double buffer, __launch_bounds__(256,2) -> <=128 regs -> 2 CTAs/SM.
// emode 0: C fp32. emode 1: qe ext [hi|hi|lo]. emode 2: ke ext [hi|lo|hi].
// ---------------------------------------------------------------------------
__global__ __launch_bounds__(256, 2) void gemm_bf16_mma(
    const __nv_bfloat16* __restrict__ A, const __nv_bfloat16* __restrict__ W,
    float* __restrict__ C, __nv_bfloat16* __restrict__ eout,
    int N, int emode, int Lrows)
{
    extern __shared__ char gsm[];
    const uint32_t smb = smem_u32(gsm);

    const int tid = threadIdx.x;
    const int wid = tid >> 5;
    const int lane = tid & 31;
    const int wm = wid & 3;
    const int wn = wid >> 2;
    const int bm = blockIdx.y * GTM;
    const int bn = blockIdx.x * GTN;

    // loaders: 2 threads per row, 4 x 16B chunks each
    const int lrow = tid >> 1;
    const int lhalf = tid & 1;
    const __nv_bfloat16* Ag = A + (size_t)(bm + lrow) * KTOT + lhalf * 32;
    const __nv_bfloat16* Wg = W + (size_t)(bn + lrow) * KTOT + lhalf * 32;
    const uint32_t lsm = lrow * GPITCH + lhalf * 64;

    float acc[2][8][4];
    #pragma unroll
    for (int mb = 0; mb < 2; mb++)
        #pragma unroll
        for (int nb = 0; nb < 8; nb++)
            #pragma unroll
            for (int i = 0; i < 4; i++) acc[mb][nb][i] = 0.f;

    const uint32_t a_row = wm * 32 + (lane & 15);
    const uint32_t a_koff = (lane >> 4) * 16;
    const uint32_t b_row = wn * 64 + (lane & 7) + 8 * ((lane >> 4) & 1);
    const uint32_t b_koff = ((lane >> 3) & 1) * 16;

    // prologue: stages 0,1
    #pragma unroll
    for (int st = 0; st < 2; st++) {
        const uint32_t ab = smb + st * STAGE;
        #pragma unroll
        for (int j = 0; j < 4; j++) {
            CP_ASYNC16(ab + lsm + j * 16, Ag + st * KB2 + j * 8);
            CP_ASYNC16(ab + ASTAGE + lsm + j * 16, Wg + st * KB2 + j * 8);
        }
        CP_COMMIT();
    }

    for (int c = 0; c < NITER2; c++) {
        const int buf = c & 1;
        CP_WAIT1();
        __syncthreads();

        const uint32_t ab = smb + buf * STAGE;
        const uint32_t bb = ab + ASTAGE;

        #pragma unroll
        for (int kk = 0; kk < 4; kk++) {
            uint32_t aF[2][4], bF[8][2];
            #pragma unroll
            for (int mb = 0; mb < 2; mb++) {
                uint32_t addr = ab + (a_row + mb * 16) * GPITCH + kk * 32 + a_koff;
                LDMATRIX_X4(aF[mb][0], aF[mb][1], aF[mb][2], aF[mb][3], addr);
            }
            #pragma unroll
            for (int nb2 = 0; nb2 < 4; nb2++) {
                uint32_t addr = bb + (b_row + nb2 * 16) * GPITCH + kk * 32 + b_koff;
                LDMATRIX_X4(bF[nb2 * 2][0], bF[nb2 * 2][1],
                            bF[nb2 * 2 + 1][0], bF[nb2 * 2 + 1][1], addr);
            }
            #pragma unroll
            for (int mb = 0; mb < 2; mb++)
                #pragma unroll
                for (int nb = 0; nb < 8; nb++)
                    MMA16816(acc[mb][nb][0], acc[mb][nb][1],
                             acc[mb][nb][2], acc[mb][nb][3],
                             aF[mb][0], aF[mb][1], aF[mb][2], aF[mb][3],
                             bF[nb][0], bF[nb][1]);
        }

        __syncthreads();
        if (c + 2 < NITER2) {
            const uint32_t pb = smb + buf * STAGE;
            #pragma unroll
            for (int j = 0; j < 4; j++) {
                CP_ASYNC16(pb + lsm + j * 16, Ag + (c + 2) * KB2 + j * 8);
                CP_ASYNC16(pb + ASTAGE + lsm + j * 16, Wg + (c + 2) * KB2 + j * 8);
            }
        }
        CP_COMMIT();
    }
    CP_WAIT0();

    const int gr = lane >> 2;
    const int gc = (lane & 3) * 2;

    if (emode == 0) {
        #pragma unroll
        for (int mb = 0; mb < 2; mb++) {
            const int row0 = bm + wm * 32 + mb * 16 + gr;
            #pragma unroll
            for (int nb = 0; nb < 8; nb++) {
                const int col = bn + wn * 64 + nb * 8 + gc;
                *(float2*)&C[(size_t)row0 * N + col] =
                    make_float2(acc[mb][nb][0], acc[mb][nb][1]);
                *(float2*)&C[(size_t)(row0 + 8) * N + col] =
                    make_float2(acc[mb][nb][2], acc[mb][nb][3]);
            }
        }
    } else {
        #pragma unroll
        for (int mb = 0; mb < 2; mb++) {
            #pragma unroll
            for (int half = 0; half < 2; half++) {
                const int row = bm + wm * 32 + mb * 16 + gr + half * 8;
                const int b = row / Lrows;
                const int t = row % Lrows;
                #pragma unroll
                for (int nb = 0; nb < 8; nb++) {
                    const int col = bn + wn * 64 + nb * 8 + gc;
                    const int h = col >> 6;
                    const int dd = col & 63;
                    float x0 = acc[mb][nb][half * 2];
                    float x1 = acc[mb][nb][half * 2 + 1];
                    __nv_bfloat16 h0 = __float2bfloat16(x0);
                    __nv_bfloat16 h1 = __float2bfloat16(x1);
                    __nv_bfloat16 l0 = __float2bfloat16(x0 - __bfloat162float(h0));
                    __nv_bfloat16 l1 = __float2bfloat16(x1 - __bfloat162float(h1));
                    __nv_bfloat16* orow =
                        eout + ((size_t)(b * H_ + h) * Lrows + t) * AKE;
                    __nv_bfloat162 hv; hv.x = h0; hv.y = h1;
                    __nv_bfloat162 lv; lv.x = l0; lv.y = l1;
                    if (emode == 1) {
                        *(__nv_bfloat162*)&orow[dd] = hv;
                        *(__nv_bfloat162*)&orow[64 + dd] = hv;
                        *(__nv_bfloat162*)&orow[128 + dd] = lv;
                    } else {
                        *(__nv_bfloat162*)&orow[dd] = hv;
                        *(__nv_bfloat162*)&orow[64 + dd] = lv;
                        *(__nv_bfloat162*)&orow[128 + dd] = hv;
                    }
                }
            }
        }
    }
}

// ---------------------------------------------------------------------------
// Tensor-core flash attention (unchanged, validated).
// ---------------------------------------------------------------------------
__global__ __launch_bounds__(256) void attn_mma(
    const __nv_bfloat16* __restrict__ qe,
    const __nv_bfloat16* __restrict__ ke,
    const __nv_bfloat16* __restrict__ vte)
{
    extern __shared__ char smraw[];
    const uint32_t sQ = smem_u32(smraw);
    const uint32_t sK = sQ + AM * APB;
    const uint32_t sV = sK + 64 * APB;

    const int tid = threadIdx.x;
    const int wid = tid >> 5;
    const int lane = tid & 31;
    const int hb = blockIdx.z;
    const int split = blockIdx.y;
    const int t0 = blockIdx.x * AM;
    const int h = hb % H_;

    const float slope = exp2f(-(float)(h + 1) / 16.0f);
    const size_t qrow0 = (size_t)hb * T_ + t0;
    const size_t krow0 = (size_t)hb * S_;
    const size_t vrow0 = (size_t)hb * 64;

    for (int idx = tid; idx < AM * 24; idx += 256) {
        int r = idx / 24, c = idx % 24;
        CP_ASYNC16(sQ + r * APB + c * 16, qe + (qrow0 + r) * AKE + c * 8);
    }
    CP_COMMIT();

    float sc[8][4], oF[8][4];
    #pragma unroll
    for (int nb = 0; nb < 8; nb++)
        #pragma unroll
        for (int i = 0; i < 4; i++) oF[nb][i] = 0.f;
    float m0 = -INFINITY, m1 = -INFINITY, l0 = 0.f, l1 = 0.f;

    const int r0 = lane >> 2;
    const float trow0 = (float)(t0 + wid * 16 + r0);
    const float trow1 = trow0 + 8.0f;

    const uint32_t a_addr_base = sQ + (wid * 16 + (lane & 15)) * APB + (lane >> 4) * 16;
    const uint32_t b_row = (lane & 7) + 8 * ((lane >> 4) & 1);
    const uint32_t b_koff = ((lane >> 3) & 1) * 16;

    const int sbeg = split * SPS;
    const int send = sbeg + SPS;

    for (int s0 = sbeg; s0 < send; s0 += 64) {
        for (int idx = tid; idx < 64 * 24; idx += 256) {
            int r = idx / 24, c = idx % 24;
            CP_ASYNC16(sK + r * APB + c * 16, ke + (krow0 + s0 + r) * AKE + c * 8);
        }
        for (int idx = tid; idx < 64 * 24; idx += 256) {
            int r = idx / 24, c = idx % 24;
            const __nv_bfloat16* vb = vte + (vrow0 + r) * (size_t)(2 * S_);
            const __nv_bfloat16* src =
                (c < 8) ? vb + s0 + c * 8
                        : (c < 16 ? vb + S_ + s0 + (c - 8) * 8
                                  : vb + s0 + (c - 16) * 8);
            CP_ASYNC16(sV + r * APB + c * 16, src);
        }
        CP_COMMIT();
        CP_WAIT0();
        __syncthreads();

        #pragma unroll
        for (int nb = 0; nb < 8; nb++)
            #pragma unroll
            for (int i = 0; i < 4; i++) sc[nb][i] = 0.f;

        #pragma unroll
        for (int ks = 0; ks < 12; ks++) {
            uint32_t aF[4], bF[8][2];
            LDMATRIX_X4(aF[0], aF[1], aF[2], aF[3], a_addr_base + ks * 32);
            #pragma unroll
            for (int nb2 = 0; nb2 < 4; nb2++) {
                uint32_t addr = sK + (b_row + nb2 * 16) * APB + ks * 32 + b_koff;
                LDMATRIX_X4(bF[nb2 * 2][0], bF[nb2 * 2][1],
                            bF[nb2 * 2 + 1][0], bF[nb2 * 2 + 1][1], addr);
            }
            #pragma unroll
            for (int nb = 0; nb < 8; nb++)
                MMA16816(sc[nb][0], sc[nb][1], sc[nb][2], sc[nb][3],
                         aF[0], aF[1], aF[2], aF[3], bF[nb][0], bF[nb][1]);
        }

        float tm0 = -INFINITY, tm1 = -INFINITY;
        #pragma unroll
        for (int nb = 0; nb < 8; nb++) {
            float scol = (float)(s0 + nb * 8 + 2 * (lane & 3));
            sc[nb][0] = sc[nb][0] * SCALE_ - slope * fabsf(trow0 - scol);
            sc[nb][1] = sc[nb][1] * SCALE_ - slope * fabsf(trow0 - (scol + 1.f));
            sc[nb][2] = sc[nb][2] * SCALE_ - slope * fabsf(trow1 - scol);
            sc[nb][3] = sc[nb][3] * SCALE_ - slope * fabsf(trow1 - (scol + 1.f));
            tm0 = fmaxf(tm0, fmaxf(sc[nb][0], sc[nb][1]));
            tm1 = fmaxf(tm1, fmaxf(sc[nb][2], sc[nb][3]));
        }
        tm0 = fmaxf(tm0, __shfl_xor_sync(0xffffffffu, tm0, 1));
        tm0 = fmaxf(tm0, __shfl_xor_sync(0xffffffffu, tm0, 2));
        tm1 = fmaxf(tm1, __shfl_xor_sync(0xffffffffu, tm1, 1));
        tm1 = fmaxf(tm1, __shfl_xor_sync(0xffffffffu, tm1, 2));

        float mn0 = fmaxf(m0, tm0);
        float mn1 = fmaxf(m1, tm1);
        float cr0 = __expf(m0 - mn0);
        float cr1 = __expf(m1 - mn1);
        l0 *= cr0; l1 *= cr1;
        #pragma unroll
        for (int nb = 0; nb < 8; nb++) {
            oF[nb][0] *= cr0; oF[nb][1] *= cr0;
            oF[nb][2] *= cr1; oF[nb][3] *= cr1;
        }

        float rs0 = 0.f, rs1 = 0.f;
        #pragma unroll
        for (int nb = 0; nb < 8; nb++) {
            sc[nb][0] = __expf(sc[nb][0] - mn0);
            sc[nb][1] = __expf(sc[nb][1] - mn0);
            sc[nb][2] = __expf(sc[nb][2] - mn1);
            sc[nb][3] = __expf(sc[nb][3] - mn1);
            rs0 += sc[nb][0] + sc[nb][1];
            rs1 += sc[nb][2] + sc[nb][3];
        }
        rs0 += __shfl_xor_sync(0xffffffffu, rs0, 1);
        rs0 += __shfl_xor_sync(0xffffffffu, rs0, 2);
        rs1 += __shfl_xor_sync(0xffffffffu, rs1, 1);
        rs1 += __shfl_xor_sync(0xffffffffu, rs1, 2);
        l0 += rs0; l1 += rs1;
        m0 = mn0; m1 = mn1;

        uint32_t phi[4][4];
        #pragma unroll
        for (int ks = 0; ks < 4; ks++) {
            phi[ks][0] = pack_bf16x2(sc[2 * ks][0], sc[2 * ks][1]);
            phi[ks][1] = pack_bf16x2(sc[2 * ks][2], sc[2 * ks][3]);
            phi[ks][2] = pack_bf16x2(sc[2 * ks + 1][0], sc[2 * ks + 1][1]);
            phi[ks][3] = pack_bf16x2(sc[2 * ks + 1][2], sc[2 * ks + 1][3]);
        }

        #pragma unroll
        for (int ks = 0; ks < 12; ks++) {
            uint32_t bF[8][2];
            #pragma unroll
            for (int nb2 = 0; nb2 < 4; nb2++) {
                uint32_t addr = sV + (b_row + nb2 * 16) * APB + ks * 32 + b_koff;
                LDMATRIX_X4(bF[nb2 * 2][0], bF[nb2 * 2][1],
                            bF[nb2 * 2 + 1][0], bF[nb2 * 2 + 1][1], addr);
            }
            uint32_t aP[4];
            if (ks < 8) {
                const int kk = ks & 3;
                aP[0] = phi[kk][0]; aP[1] = phi[kk][1];
                aP[2] = phi[kk][2]; aP[3] = phi[kk][3];
            } else {
                const int kk = ks - 8;
                #pragma unroll
                for (int j = 0; j < 4; j++) {
                    const int nb = 2 * kk + (j >> 1);
                    const int ci = (j & 1) * 2;
                    float pe = sc[nb][ci]     - bf16lo_f(phi[kk][j]);
                    float po = sc[nb][ci + 1] - bf16hi_f(phi[kk][j]);
                    aP[j] = pack_bf16x2(pe, po);
                }
            }
            #pragma unroll
            for (int nb = 0; nb < 8; nb++)
                MMA16816(oF[nb][0], oF[nb][1], oF[nb][2], oF[nb][3],
                         aP[0], aP[1], aP[2], aP[3], bF[nb][0], bF[nb][1]);
        }
        __syncthreads();
    }

    const size_t base = (size_t)(split * B_ * H_ + hb) * T_;
    const size_t pidx0 = base + t0 + wid * 16 + r0;
    const size_t pidx1 = pidx0 + 8;
    #pragma unroll
    for (int nb = 0; nb < 8; nb++) {
        const int col = nb * 8 + 2 * (lane & 3);
        *(float2*)&g_pacc[pidx0 * HD_ + col] = make_float2(oF[nb][0], oF[nb][1]);
        *(float2*)&g_pacc[pidx1 * HD_ + col] = make_float2(oF[nb][2], oF[nb][3]);
    }
    if ((lane & 3) == 0) {
        g_pm[pidx0] = m0; g_pl[pidx0] = l0;
        g_pm[pidx1] = m1; g_pl[pidx1] = l1;
    }
}

// ---------------------------------------------------------------------------
// Combine split-KV partials -> split-act layout (unchanged)
// ---------------------------------------------------------------------------
__global__ __launch_bounds__(256) void attn_combine_kernel(
    __nv_bfloat16* __restrict__ as_out)
{
    const int d = threadIdx.x & 63;
    const int rlocal = threadIdx.x >> 6;
    const size_t row = (size_t)blockIdx.x * 4 + rlocal;
    const int t = row % T_;
    const int h = (row / T_) % H_;
    const int b = row / ((size_t)T_ * H_);

    float m0 = g_pm[row];
    float l0 = g_pl[row];
    float m1 = g_pm[(size_t)B_ * H_ * T_ + row];
    float l1 = g_pl[(size_t)B_ * H_ * T_ + row];

    float M = fmaxf(m0, m1);
    float e0 = __expf(m0 - M), e1 = __expf(m1 - M);
    float L = l0 * e0 + l1 * e1;
    float inv = 1.f / L;

    float a0 = g_pacc[row * HD_ + d];
    float a1 = g_pacc[((size_t)B_ * H_ * T_ + row) * HD_ + d];
    float val = (a0 * e0 + a1 * e1) * inv;

    __nv_bfloat16 hi = __float2bfloat16(val);
    __nv_bfloat16 lo = __float2bfloat16(val - __bfloat162float(hi));
    const int c = h * 64 + d;
    __nv_bfloat16* orow = as_out + ((size_t)(b * T_ + t)) * KTOT;
    orow[c] = hi; orow[D_ + c] = hi; orow[2 * D_ + c] = lo;
}

// ---------------------------------------------------------------------------
// residual + RMSNorm (unchanged)
// ---------------------------------------------------------------------------
__global__ __launch_bounds__(256) void rms_kernel(
    const float* __restrict__ query, const float* __restrict__ proj,
    const float* __restrict__ w, float* __restrict__ out)
{
    __shared__ float sh[8];
    __shared__ float s_inv;
    const size_t row = blockIdx.x;
    const float* qr = query + row * D_;
    const float* pr = proj + row * D_;
    float* orow = out + row * D_;

    float x[4];
    float ss = 0.f;
    #pragma unroll
    for (int i = 0; i < 4; i++) {
        int idx = threadIdx.x + i * 256;
        x[i] = qr[idx] + pr[idx];
        ss += x[i] * x[i];
    }
    #pragma unroll
    for (int ofs = 16; ofs > 0; ofs >>= 1)
        ss += __shfl_xor_sync(0xffffffffu, ss, ofs);
    const int lane = threadIdx.x & 31, wid = threadIdx.x >> 5;
    if (lane == 0) sh[wid] = ss;
    __syncthreads();
    if (threadIdx.x == 0) {
        float tot = 0.f;
        #pragma unroll
        for (int i = 0; i < 8; i++) tot += sh[i];
        s_inv = rsqrtf(tot * (1.0f / D_) + RMS_EPS_);
    }
    __syncthreads();
    const float inv = s_inv;
    #pragma unroll
    for (int i = 0; i < 4; i++) {
        int idx = threadIdx.x + i * 256;
        orow[idx] = x[i] * inv * w[idx];
    }
}

// ---------------------------------------------------------------------------
extern "C" void kernel_launch(void* const* d_in, const int* in_sizes, int n_in,
                              void* d_out, int out_size)
{
    const float* query   = (const float*)d_in[0];
    const float* context = (const float*)d_in[1];
    const float* Wq      = (const float*)d_in[2];
    const float* Wk      = (const float*)d_in[3];
    const float* Wv      = (const float*)d_in[4];
    const float* Wo      = (const float*)d_in[5];
    const float* rmsw    = (const float*)d_in[6];
    float* out = (float*)d_out;

    float *pv, *pproj;
    cudaGetSymbolAddress((void**)&pv,    g_v);
    cudaGetSymbolAddress((void**)&pproj, g_proj);

    __nv_bfloat16 *qs, *cs, *as, *wqs, *wks, *wvs, *wos, *qe, *kke, *vte;
    cudaGetSymbolAddress((void**)&qs,  g_qs);
    cudaGetSymbolAddress((void**)&cs,  g_cs);
    cudaGetSymbolAddress((void**)&as,  g_as);
    cudaGetSymbolAddress((void**)&wqs, g_wqs);
    cudaGetSymbolAddress((void**)&wks, g_wks);
    cudaGetSymbolAddress((void**)&wvs, g_wvs);
    cudaGetSymbolAddress((void**)&wos, g_wos);
    cudaGetSymbolAddress((void**)&qe,  g_qe);
    cudaGetSymbolAddress((void**)&kke, g_ke);
    cudaGetSymbolAddress((void**)&vte, g_vte);

    cudaFuncSetAttribute(gemm_bf16_mma,
        cudaFuncAttributeMaxDynamicSharedMemorySize, GEMM_SMEM);
    cudaFuncSetAttribute(attn_mma,
        cudaFuncAttributeMaxDynamicSharedMemorySize, ATTN_SMEM);

    const int MQ = B_ * T_;   // 2048
    const int MK = B_ * S_;   // 4096

    // all input conversions in one launch
    split_all<<<10240, 256>>>(query, context, Wq, Wk, Wv, Wo);

    // projections — all 128x128 tiles, 2 CTAs/SM
    dim3 gq(D_ / GTN, MQ / GTM);   // 8 x 16 = 128 CTAs
    dim3 gk(D_ / GTN, MK / GTM);   // 8 x 32 = 256 CTAs
    gemm_bf16_mma<<<gq, 256, GEMM_SMEM>>>(qs, wqs, nullptr, qe,  D_, 1, T_);
    gemm_bf16_mma<<<gk, 256, GEMM_SMEM>>>(cs, wks, nullptr, kke, D_, 2, S_);
    gemm_bf16_mma<<<gk, 256, GEMM_SMEM>>>(cs, wvs, pv, nullptr,  D_, 0, 0);

    v_ext_t<<<dim3(S_ / 32, 2, B_ * H_), dim3(32, 8)>>>(pv, vte);

    // tensor-core attention
    attn_mma<<<dim3(T_ / AM, NS_, B_ * H_), 256, ATTN_SMEM>>>(qe, kke, vte);
    attn_combine_kernel<<<(B_ * H_ * T_) / 4, 256>>>(as);

    // output projection
    gemm_bf16_mma<<<gq, 256, GEMM_SMEM>>>(as, wos, pproj, nullptr, D_, 0, 0);

    rms_kernel<<<MQ, 256>>>(query, pproj, rmsw, out);
}

// round 15
// speedup vs baseline: 1.6522x; 1.2203x over previous
#include <cuda_runtime.h>
#include <cuda_bf16.h>
#include <math.h>
#include <stdint.h>

// Problem constants
#define B_  2
#define T_  1024
#define S_  2048
#define D_  1024
#define H_  16
#define HD_ 64
#define SCALE_ 0.125f
#define RMS_EPS_ 1e-6f

#define NS_ 2
#define SPS (S_ / NS_)

// hi/lo split GEMM config (3 products from 2K of data)
#define KD 1024                   // useful K
#define KB 32                     // useful k per stage
#define NSTG (KD / KB)            // 32 stages
#define GTM 128
#define GTN 128
#define GP2 80                    // smem row pitch bytes (64B data + 16 pad)
#define ASTG (GTM * GP2)          // 10240 per array
#define STAGE (4 * ASTG)          // Ahi,Alo,Whi,Wlo = 40960
#define GEMM_SMEM (2 * STAGE)     // 81920 -> 2 CTAs/SM

// attention mma config
#define AM 128
#define AKE 192
#define APB 400
#define ATTN_SMEM ((AM + 64 + 64) * APB)  // 102400

// Scratch (device globals; no allocation allowed)
__device__ float g_v[B_ * S_ * D_];
__device__ float g_proj[B_ * T_ * D_];
__device__ float g_pacc[NS_ * B_ * H_ * T_ * HD_];
__device__ float g_pm[NS_ * B_ * H_ * T_];
__device__ float g_pl[NS_ * B_ * H_ * T_];
// hi/lo split operands
__device__ __nv_bfloat16 g_qsh[(size_t)B_ * T_ * KD];
__device__ __nv_bfloat16 g_qsl[(size_t)B_ * T_ * KD];
__device__ __nv_bfloat16 g_csh[(size_t)B_ * S_ * KD];
__device__ __nv_bfloat16 g_csl[(size_t)B_ * S_ * KD];
__device__ __nv_bfloat16 g_ash[(size_t)B_ * T_ * KD];
__device__ __nv_bfloat16 g_asl[(size_t)B_ * T_ * KD];
__device__ __nv_bfloat16 g_wqh[(size_t)D_ * KD];
__device__ __nv_bfloat16 g_wql[(size_t)D_ * KD];
__device__ __nv_bfloat16 g_wkh[(size_t)D_ * KD];
__device__ __nv_bfloat16 g_wkl[(size_t)D_ * KD];
__device__ __nv_bfloat16 g_wvh[(size_t)D_ * KD];
__device__ __nv_bfloat16 g_wvl[(size_t)D_ * KD];
__device__ __nv_bfloat16 g_woh[(size_t)D_ * KD];
__device__ __nv_bfloat16 g_wol[(size_t)D_ * KD];
// attention extended operands (unchanged layouts)
__device__ __nv_bfloat16 g_qe[(size_t)B_ * H_ * T_ * AKE];        // [qhi|qhi|qlo]
__device__ __nv_bfloat16 g_ke[(size_t)B_ * H_ * S_ * AKE];        // [khi|klo|khi]
__device__ __nv_bfloat16 g_vte[(size_t)B_ * H_ * HD_ * 2 * S_];   // V^T [d][hi(S)|lo(S)]

// ============================ PTX helpers (base ISA) ========================
__device__ __forceinline__ uint32_t smem_u32(const void* p) {
    uint32_t a;
    asm("{ .reg .u64 t; cvta.to.shared.u64 t, %1; cvt.u32.u64 %0, t; }"
        : "=r"(a) : "l"(p));
    return a;
}

#define CP_ASYNC16(dst_u32, src_ptr) \
    asm volatile("cp.async.cg.shared.global [%0], [%1], 16;" \
        :: "r"(dst_u32), "l"(src_ptr))
#define CP_COMMIT() asm volatile("cp.async.commit_group;" ::: "memory")
#define CP_WAIT1()  asm volatile("cp.async.wait_group 1;" ::: "memory")
#define CP_WAIT0()  asm volatile("cp.async.wait_group 0;" ::: "memory")

#define LDMATRIX_X4(r0, r1, r2, r3, addr) \
    asm volatile("ldmatrix.sync.aligned.m8n8.x4.shared.b16 {%0,%1,%2,%3}, [%4];" \
        : "=r"(r0), "=r"(r1), "=r"(r2), "=r"(r3) : "r"(addr))

#define MMA16816(d0, d1, d2, d3, a0, a1, a2, a3, b0, b1) \
    asm volatile("mma.sync.aligned.m16n8k16.row.col.f32.bf16.bf16.f32 " \
        "{%0,%1,%2,%3}, {%4,%5,%6,%7}, {%8,%9}, {%0,%1,%2,%3};" \
        : "+f"(d0), "+f"(d1), "+f"(d2), "+f"(d3) \
        : "r"(a0), "r"(a1), "r"(a2), "r"(a3), "r"(b0), "r"(b1))

__device__ __forceinline__ uint32_t pack_bf16x2(float p0, float p1) {
    uint32_t d;
    asm("cvt.rn.bf16x2.f32 %0, %1, %2;" : "=r"(d) : "f"(p1), "f"(p0));
    return d;
}
__device__ __forceinline__ float bf16lo_f(uint32_t u) {
    return __uint_as_float(u << 16);
}
__device__ __forceinline__ float bf16hi_f(uint32_t u) {
    return __uint_as_float(u & 0xffff0000u);
}

// ---------------------------------------------------------------------------
// Mega split kernel: fp32 row -> (hi, lo) bf16 rows. One launch for all.
//  [0,2048): query -> g_qsh/g_qsl ; [2048,6144): context -> g_csh/g_csl ;
//  [6144,10240): weights -> g_w{q,k,v,o}{h,l}
// ---------------------------------------------------------------------------
__global__ __launch_bounds__(256) void split_all(
    const float* __restrict__ query, const float* __restrict__ context,
    const float* __restrict__ Wq, const float* __restrict__ Wk,
    const float* __restrict__ Wv, const float* __restrict__ Wo)
{
    const int bid = blockIdx.x;
    const float* in;
    __nv_bfloat16 *oh, *ol;
    if (bid < 2048) {
        in = query + (size_t)bid * D_;
        oh = g_qsh + (size_t)bid * KD;
        ol = g_qsl + (size_t)bid * KD;
    } else if (bid < 6144) {
        int r = bid - 2048;
        in = context + (size_t)r * D_;
        oh = g_csh + (size_t)r * KD;
        ol = g_csl + (size_t)r * KD;
    } else {
        int idx = bid - 6144;
        int w = idx >> 10;
        int r = idx & 1023;
        const float* Ws[4] = {Wq, Wk, Wv, Wo};
        __nv_bfloat16* Hs[4] = {g_wqh, g_wkh, g_wvh, g_woh};
        __nv_bfloat16* Ls[4] = {g_wql, g_wkl, g_wvl, g_wol};
        in = Ws[w] + (size_t)r * D_;
        oh = Hs[w] + (size_t)r * KD;
        ol = Ls[w] + (size_t)r * KD;
    }
    #pragma unroll
    for (int i = 0; i < 4; i++) {
        int c = threadIdx.x + i * 256;
        float x = in[c];
        __nv_bfloat16 hi = __float2bfloat16(x);
        __nv_bfloat16 lo = __float2bfloat16(x - __bfloat162float(hi));
        oh[c] = hi;
        ol[c] = lo;
    }
}

// v_ext_t (validated; duplicate store cleaned)
__global__ __launch_bounds__(256) void v_ext_t(
    const float* __restrict__ v, __nv_bfloat16* __restrict__ out)
{
    __shared__ float tile[32][33];
    const int s0 = blockIdx.x * 32;
    const int d0 = blockIdx.y * 32;
    const int bh = blockIdx.z;
    const int b = bh / H_;
    const int h = bh % H_;
    const int tx = threadIdx.x, ty = threadIdx.y;
    #pragma unroll
    for (int i = 0; i < 4; i++) {
        int s = s0 + ty + i * 8;
        tile[ty + i * 8][tx] = v[((size_t)(b * S_ + s)) * D_ + h * 64 + d0 + tx];
    }
    __syncthreads();
    #pragma unroll
    for (int i = 0; i < 4; i++) {
        int d = d0 + ty + i * 8;
        float x = tile[tx][ty + i * 8];
        __nv_bfloat16 hi = __float2bfloat16(x);
        __nv_bfloat16 lo = __float2bfloat16(x - __bfloat162float(hi));
        __nv_bfloat16* orow = out + ((size_t)(bh * 64 + d)) * (2 * S_);
        orow[s0 + tx] = hi;
        orow[S_ + s0 + tx] = lo;
    }
}

// ---------------------------------------------------------------------------
// hi/lo-split bf16 mma.sync GEMM: C = Ah·Wh^T + Ah·Wl^T + Al·Wh^T
// 128x128 tile, 256 threads (4M x 2N warps), KB=32 stage, 2-stage buffer.
// Per kk(16): 12 LDSM, 48 MMA  (vs 18 LDSM in the concatenated-K scheme).
// emode 0: C fp32. emode 1: qe ext [hi|hi|lo]. emode 2: ke ext [hi|lo|hi].
// ---------------------------------------------------------------------------
__global__ __launch_bounds__(256, 2) void gemm_bf16_mma(
    const __nv_bfloat16* __restrict__ Ah, const __nv_bfloat16* __restrict__ Al,
    const __nv_bfloat16* __restrict__ Wh, const __nv_bfloat16* __restrict__ Wl,
    float* __restrict__ C, __nv_bfloat16* __restrict__ eout,
    int N, int emode, int Lrows)
{
    extern __shared__ char gsm[];
    const uint32_t smb = smem_u32(gsm);

    const int tid = threadIdx.x;
    const int wid = tid >> 5;
    const int lane = tid & 31;
    const int wm = wid & 3;
    const int wn = wid >> 2;
    const int bm = blockIdx.y * GTM;
    const int bn = blockIdx.x * GTN;

    // loaders: 2 threads per row; each thread 2 chunks per array
    const int lrow = tid >> 1;
    const int lsub = tid & 1;
    const size_t arow = (size_t)(bm + lrow) * KD + lsub * 16;
    const size_t wrow = (size_t)(bn + lrow) * KD + lsub * 16;
    const __nv_bfloat16* gAh = Ah + arow;
    const __nv_bfloat16* gAl = Al + arow;
    const __nv_bfloat16* gWh = Wh + wrow;
    const __nv_bfloat16* gWl = Wl + wrow;
    const uint32_t lsm = lrow * GP2 + lsub * 32;

    float acc[2][8][4];
    #pragma unroll
    for (int mb = 0; mb < 2; mb++)
        #pragma unroll
        for (int nb = 0; nb < 8; nb++)
            #pragma unroll
            for (int i = 0; i < 4; i++) acc[mb][nb][i] = 0.f;

    const uint32_t a_row = wm * 32 + (lane & 15);
    const uint32_t a_koff = (lane >> 4) * 16;
    const uint32_t b_row = wn * 64 + (lane & 7) + 8 * ((lane >> 4) & 1);
    const uint32_t b_koff = ((lane >> 3) & 1) * 16;

    // prologue: stages 0,1
    #pragma unroll
    for (int st = 0; st < 2; st++) {
        const uint32_t sb = smb + st * STAGE;
        #pragma unroll
        for (int j = 0; j < 2; j++) {
            CP_ASYNC16(sb + 0 * ASTG + lsm + j * 16, gAh + st * KB + j * 8);
            CP_ASYNC16(sb + 1 * ASTG + lsm + j * 16, gAl + st * KB + j * 8);
            CP_ASYNC16(sb + 2 * ASTG + lsm + j * 16, gWh + st * KB + j * 8);
            CP_ASYNC16(sb + 3 * ASTG + lsm + j * 16, gWl + st * KB + j * 8);
        }
        CP_COMMIT();
    }

    for (int c = 0; c < NSTG; c++) {
        const int buf = c & 1;
        CP_WAIT1();
        __syncthreads();

        const uint32_t sb = smb + buf * STAGE;
        const uint32_t bAh = sb + 0 * ASTG;
        const uint32_t bAl = sb + 1 * ASTG;
        const uint32_t bWh = sb + 2 * ASTG;
        const uint32_t bWl = sb + 3 * ASTG;

        #pragma unroll
        for (int kk = 0; kk < 2; kk++) {
            uint32_t ah[2][4], al[2][4], wf[8][2];
            #pragma unroll
            for (int mb = 0; mb < 2; mb++) {
                uint32_t ro = (a_row + mb * 16) * GP2 + kk * 32 + a_koff;
                LDMATRIX_X4(ah[mb][0], ah[mb][1], ah[mb][2], ah[mb][3], bAh + ro);
                LDMATRIX_X4(al[mb][0], al[mb][1], al[mb][2], al[mb][3], bAl + ro);
            }
            // --- Whi: Ahi*Whi + Alo*Whi ---
            #pragma unroll
            for (int nb2 = 0; nb2 < 4; nb2++) {
                uint32_t ro = (b_row + nb2 * 16) * GP2 + kk * 32 + b_koff;
                LDMATRIX_X4(wf[nb2 * 2][0], wf[nb2 * 2][1],
                            wf[nb2 * 2 + 1][0], wf[nb2 * 2 + 1][1], bWh + ro);
            }
            #pragma unroll
            for (int mb = 0; mb < 2; mb++)
                #pragma unroll
                for (int nb = 0; nb < 8; nb++)
                    MMA16816(acc[mb][nb][0], acc[mb][nb][1],
                             acc[mb][nb][2], acc[mb][nb][3],
                             ah[mb][0], ah[mb][1], ah[mb][2], ah[mb][3],
                             wf[nb][0], wf[nb][1]);
            #pragma unroll
            for (int mb = 0; mb < 2; mb++)
                #pragma unroll
                for (int nb = 0; nb < 8; nb++)
                    MMA16816(acc[mb][nb][0], acc[mb][nb][1],
                             acc[mb][nb][2], acc[mb][nb][3],
                             al[mb][0], al[mb][1], al[mb][2], al[mb][3],
                             wf[nb][0], wf[nb][1]);
            // --- Wlo: Ahi*Wlo ---
            #pragma unroll
            for (int nb2 = 0; nb2 < 4; nb2++) {
                uint32_t ro = (b_row + nb2 * 16) * GP2 + kk * 32 + b_koff;
                LDMATRIX_X4(wf[nb2 * 2][0], wf[nb2 * 2][1],
                            wf[nb2 * 2 + 1][0], wf[nb2 * 2 + 1][1], bWl + ro);
            }
            #pragma unroll
            for (int mb = 0; mb < 2; mb++)
                #pragma unroll
                for (int nb = 0; nb < 8; nb++)
                    MMA16816(acc[mb][nb][0], acc[mb][nb][1],
                             acc[mb][nb][2], acc[mb][nb][3],
                             ah[mb][0], ah[mb][1], ah[mb][2], ah[mb][3],
                             wf[nb][0], wf[nb][1]);
        }

        __syncthreads();
        if (c + 2 < NSTG) {
            const uint32_t pb = smb + buf * STAGE;
            #pragma unroll
            for (int j = 0; j < 2; j++) {
                CP_ASYNC16(pb + 0 * ASTG + lsm + j * 16, gAh + (c + 2) * KB + j * 8);
                CP_ASYNC16(pb + 1 * ASTG + lsm + j * 16, gAl + (c + 2) * KB + j * 8);
                CP_ASYNC16(pb + 2 * ASTG + lsm + j * 16, gWh + (c + 2) * KB + j * 8);
                CP_ASYNC16(pb + 3 * ASTG + lsm + j * 16, gWl + (c + 2) * KB + j * 8);
            }
        }
        CP_COMMIT();
    }
    CP_WAIT0();

    const int gr = lane >> 2;
    const int gc = (lane & 3) * 2;

    if (emode == 0) {
        #pragma unroll
        for (int mb = 0; mb < 2; mb++) {
            const int row0 = bm + wm * 32 + mb * 16 + gr;
            #pragma unroll
            for (int nb = 0; nb < 8; nb++) {
                const int col = bn + wn * 64 + nb * 8 + gc;
                *(float2*)&C[(size_t)row0 * N + col] =
                    make_float2(acc[mb][nb][0], acc[mb][nb][1]);
                *(float2*)&C[(size_t)(row0 + 8) * N + col] =
                    make_float2(acc[mb][nb][2], acc[mb][nb][3]);
            }
        }
    } else {
        #pragma unroll
        for (int mb = 0; mb < 2; mb++) {
            #pragma unroll
            for (int half = 0; half < 2; half++) {
                const int row = bm + wm * 32 + mb * 16 + gr + half * 8;
                const int b = row / Lrows;
                const int t = row % Lrows;
                #pragma unroll
                for (int nb = 0; nb < 8; nb++) {
                    const int col = bn + wn * 64 + nb * 8 + gc;
                    const int h = col >> 6;
                    const int dd = col & 63;
                    float x0 = acc[mb][nb][half * 2];
                    float x1 = acc[mb][nb][half * 2 + 1];
                    __nv_bfloat16 h0 = __float2bfloat16(x0);
                    __nv_bfloat16 h1 = __float2bfloat16(x1);
                    __nv_bfloat16 l0 = __float2bfloat16(x0 - __bfloat162float(h0));
                    __nv_bfloat16 l1 = __float2bfloat16(x1 - __bfloat162float(h1));
                    __nv_bfloat16* orow =
                        eout + ((size_t)(b * H_ + h) * Lrows + t) * AKE;
                    __nv_bfloat162 hv; hv.x = h0; hv.y = h1;
                    __nv_bfloat162 lv; lv.x = l0; lv.y = l1;
                    if (emode == 1) {
                        *(__nv_bfloat162*)&orow[dd] = hv;
                        *(__nv_bfloat162*)&orow[64 + dd] = hv;
                        *(__nv_bfloat162*)&orow[128 + dd] = lv;
                    } else {
                        *(__nv_bfloat162*)&orow[dd] = hv;
                        *(__nv_bfloat162*)&orow[64 + dd] = lv;
                        *(__nv_bfloat162*)&orow[128 + dd] = hv;
                    }
                }
            }
        }
    }
}

// ---------------------------------------------------------------------------
// Tensor-core flash attention (unchanged, validated).
// ---------------------------------------------------------------------------
__global__ __launch_bounds__(256) void attn_mma(
    const __nv_bfloat16* __restrict__ qe,
    const __nv_bfloat16* __restrict__ ke,
    const __nv_bfloat16* __restrict__ vte)
{
    extern __shared__ char smraw[];
    const uint32_t sQ = smem_u32(smraw);
    const uint32_t sK = sQ + AM * APB;
    const uint32_t sV = sK + 64 * APB;

    const int tid = threadIdx.x;
    const int wid = tid >> 5;
    const int lane = tid & 31;
    const int hb = blockIdx.z;
    const int split = blockIdx.y;
    const int t0 = blockIdx.x * AM;
    const int h = hb % H_;

    const float slope = exp2f(-(float)(h + 1) / 16.0f);
    const size_t qrow0 = (size_t)hb * T_ + t0;
    const size_t krow0 = (size_t)hb * S_;
    const size_t vrow0 = (size_t)hb * 64;

    for (int idx = tid; idx < AM * 24; idx += 256) {
        int r = idx / 24, c = idx % 24;
        CP_ASYNC16(sQ + r * APB + c * 16, qe + (qrow0 + r) * AKE + c * 8);
    }
    CP_COMMIT();

    float sc[8][4], oF[8][4];
    #pragma unroll
    for (int nb = 0; nb < 8; nb++)
        #pragma unroll
        for (int i = 0; i < 4; i++) oF[nb][i] = 0.f;
    float m0 = -INFINITY, m1 = -INFINITY, l0 = 0.f, l1 = 0.f;

    const int r0 = lane >> 2;
    const float trow0 = (float)(t0 + wid * 16 + r0);
    const float trow1 = trow0 + 8.0f;

    const uint32_t a_addr_base = sQ + (wid * 16 + (lane & 15)) * APB + (lane >> 4) * 16;
    const uint32_t b_row = (lane & 7) + 8 * ((lane >> 4) & 1);
    const uint32_t b_koff = ((lane >> 3) & 1) * 16;

    const int sbeg = split * SPS;
    const int send = sbeg + SPS;

    for (int s0 = sbeg; s0 < send; s0 += 64) {
        for (int idx = tid; idx < 64 * 24; idx += 256) {
            int r = idx / 24, c = idx % 24;
            CP_ASYNC16(sK + r * APB + c * 16, ke + (krow0 + s0 + r) * AKE + c * 8);
        }
        for (int idx = tid; idx < 64 * 24; idx += 256) {
            int r = idx / 24, c = idx % 24;
            const __nv_bfloat16* vb = vte + (vrow0 + r) * (size_t)(2 * S_);
            const __nv_bfloat16* src =
                (c < 8) ? vb + s0 + c * 8
                        : (c < 16 ? vb + S_ + s0 + (c - 8) * 8
                                  : vb + s0 + (c - 16) * 8);
            CP_ASYNC16(sV + r * APB + c * 16, src);
        }
        CP_COMMIT();
        CP_WAIT0();
        __syncthreads();

        #pragma unroll
        for (int nb = 0; nb < 8; nb++)
            #pragma unroll
            for (int i = 0; i < 4; i++) sc[nb][i] = 0.f;

        #pragma unroll
        for (int ks = 0; ks < 12; ks++) {
            uint32_t aF[4], bF[8][2];
            LDMATRIX_X4(aF[0], aF[1], aF[2], aF[3], a_addr_base + ks * 32);
            #pragma unroll
            for (int nb2 = 0; nb2 < 4; nb2++) {
                uint32_t addr = sK + (b_row + nb2 * 16) * APB + ks * 32 + b_koff;
                LDMATRIX_X4(bF[nb2 * 2][0], bF[nb2 * 2][1],
                            bF[nb2 * 2 + 1][0], bF[nb2 * 2 + 1][1], addr);
            }
            #pragma unroll
            for (int nb = 0; nb < 8; nb++)
                MMA16816(sc[nb][0], sc[nb][1], sc[nb][2], sc[nb][3],
                         aF[0], aF[1], aF[2], aF[3], bF[nb][0], bF[nb][1]);
        }

        float tm0 = -INFINITY, tm1 = -INFINITY;
        #pragma unroll
        for (int nb = 0; nb < 8; nb++) {
            float scol = (float)(s0 + nb * 8 + 2 * (lane & 3));
            sc[nb][0] = sc[nb][0] * SCALE_ - slope * fabsf(trow0 - scol);
            sc[nb][1] = sc[nb][1] * SCALE_ - slope * fabsf(trow0 - (scol + 1.f));
            sc[nb][2] = sc[nb][2] * SCALE_ - slope * fabsf(trow1 - scol);
            sc[nb][3] = sc[nb][3] * SCALE_ - slope * fabsf(trow1 - (scol + 1.f));
            tm0 = fmaxf(tm0, fmaxf(sc[nb][0], sc[nb][1]));
            tm1 = fmaxf(tm1, fmaxf(sc[nb][2], sc[nb][3]));
        }
        tm0 = fmaxf(tm0, __shfl_xor_sync(0xffffffffu, tm0, 1));
        tm0 = fmaxf(tm0, __shfl_xor_sync(0xffffffffu, tm0, 2));
        tm1 = fmaxf(tm1, __shfl_xor_sync(0xffffffffu, tm1, 1));
        tm1 = fmaxf(tm1, __shfl_xor_sync(0xffffffffu, tm1, 2));

        float mn0 = fmaxf(m0, tm0);
        float mn1 = fmaxf(m1, tm1);
        float cr0 = __expf(m0 - mn0);
        float cr1 = __expf(m1 - mn1);
        l0 *= cr0; l1 *= cr1;
        #pragma unroll
        for (int nb = 0; nb < 8; nb++) {
            oF[nb][0] *= cr0; oF[nb][1] *= cr0;
            oF[nb][2] *= cr1; oF[nb][3] *= cr1;
        }

        float rs0 = 0.f, rs1 = 0.f;
        #pragma unroll
        for (int nb = 0; nb < 8; nb++) {
            sc[nb][0] = __expf(sc[nb][0] - mn0);
            sc[nb][1] = __expf(sc[nb][1] - mn0);
            sc[nb][2] = __expf(sc[nb][2] - mn1);
            sc[nb][3] = __expf(sc[nb][3] - mn1);
            rs0 += sc[nb][0] + sc[nb][1];
            rs1 += sc[nb][2] + sc[nb][3];
        }
        rs0 += __shfl_xor_sync(0xffffffffu, rs0, 1);
        rs0 += __shfl_xor_sync(0xffffffffu, rs0, 2);
        rs1 += __shfl_xor_sync(0xffffffffu, rs1, 1);
        rs1 += __shfl_xor_sync(0xffffffffu, rs1, 2);
        l0 += rs0; l1 += rs1;
        m0 = mn0; m1 = mn1;

        uint32_t phi[4][4];
        #pragma unroll
        for (int ks = 0; ks < 4; ks++) {
            phi[ks][0] = pack_bf16x2(sc[2 * ks][0], sc[2 * ks][1]);
            phi[ks][1] = pack_bf16x2(sc[2 * ks][2], sc[2 * ks][3]);
            phi[ks][2] = pack_bf16x2(sc[2 * ks + 1][0], sc[2 * ks + 1][1]);
            phi[ks][3] = pack_bf16x2(sc[2 * ks + 1][2], sc[2 * ks + 1][3]);
        }

        #pragma unroll
        for (int ks = 0; ks < 12; ks++) {
            uint32_t bF[8][2];
            #pragma unroll
            for (int nb2 = 0; nb2 < 4; nb2++) {
                uint32_t addr = sV + (b_row + nb2 * 16) * APB + ks * 32 + b_koff;
                LDMATRIX_X4(bF[nb2 * 2][0], bF[nb2 * 2][1],
                            bF[nb2 * 2 + 1][0], bF[nb2 * 2 + 1][1], addr);
            }
            uint32_t aP[4];
            if (ks < 8) {
                const int kk = ks & 3;
                aP[0] = phi[kk][0]; aP[1] = phi[kk][1];
                aP[2] = phi[kk][2]; aP[3] = phi[kk][3];
            } else {
                const int kk = ks - 8;
                #pragma unroll
                for (int j = 0; j < 4; j++) {
                    const int nb = 2 * kk + (j >> 1);
                    const int ci = (j & 1) * 2;
                    float pe = sc[nb][ci]     - bf16lo_f(phi[kk][j]);
                    float po = sc[nb][ci + 1] - bf16hi_f(phi[kk][j]);
                    aP[j] = pack_bf16x2(pe, po);
                }
            }
            #pragma unroll
            for (int nb = 0; nb < 8; nb++)
                MMA16816(oF[nb][0], oF[nb][1], oF[nb][2], oF[nb][3],
                         aP[0], aP[1], aP[2], aP[3], bF[nb][0], bF[nb][1]);
        }
        __syncthreads();
    }

    const size_t base = (size_t)(split * B_ * H_ + hb) * T_;
    const size_t pidx0 = base + t0 + wid * 16 + r0;
    const size_t pidx1 = pidx0 + 8;
    #pragma unroll
    for (int nb = 0; nb < 8; nb++) {
        const int col = nb * 8 + 2 * (lane & 3);
        *(float2*)&g_pacc[pidx0 * HD_ + col] = make_float2(oF[nb][0], oF[nb][1]);
        *(float2*)&g_pacc[pidx1 * HD_ + col] = make_float2(oF[nb][2], oF[nb][3]);
    }
    if ((lane & 3) == 0) {
        g_pm[pidx0] = m0; g_pl[pidx0] = l0;
        g_pm[pidx1] = m1; g_pl[pidx1] = l1;
    }
}

// ---------------------------------------------------------------------------
// Combine split-KV partials -> hi/lo split rows (g_ash/g_asl)
// ---------------------------------------------------------------------------
__global__ __launch_bounds__(256) void attn_combine_kernel(
    __nv_bfloat16* __restrict__ ash, __nv_bfloat16* __restrict__ asl)
{
    const int d = threadIdx.x & 63;
    const int rlocal = threadIdx.x >> 6;
    const size_t row = (size_t)blockIdx.x * 4 + rlocal;
    const int t = row % T_;
    const int h = (row / T_) % H_;
    const int b = row / ((size_t)T_ * H_);

    float m0 = g_pm[row];
    float l0 = g_pl[row];
    float m1 = g_pm[(size_t)B_ * H_ * T_ + row];
    float l1 = g_pl[(size_t)B_ * H_ * T_ + row];

    float M = fmaxf(m0, m1);
    float e0 = __expf(m0 - M), e1 = __expf(m1 - M);
    float L = l0 * e0 + l1 * e1;
    float inv = 1.f / L;

    float a0 = g_pacc[row * HD_ + d];
    float a1 = g_pacc[((size_t)B_ * H_ * T_ + row) * HD_ + d];
    float val = (a0 * e0 + a1 * e1) * inv;

    __nv_bfloat16 hi = __float2bfloat16(val);
    __nv_bfloat16 lo = __float2bfloat16(val - __bfloat162float(hi));
    const int c = h * 64 + d;
    const size_t ro = (size_t)(b * T_ + t) * KD;
    ash[ro + c] = hi;
    asl[ro + c] = lo;
}

// ---------------------------------------------------------------------------
// residual + RMSNorm (unchanged)
// ---------------------------------------------------------------------------
__global__ __launch_bounds__(256) void rms_kernel(
    const float* __restrict__ query, const float* __restrict__ proj,
    const float* __restrict__ w, float* __restrict__ out)
{
    __shared__ float sh[8];
    __shared__ float s_inv;
    const size_t row = blockIdx.x;
    const float* qr = query + row * D_;
    const float* pr = proj + row * D_;
    float* orow = out + row * D_;

    float x[4];
    float ss = 0.f;
    #pragma unroll
    for (int i = 0; i < 4; i++) {
        int idx = threadIdx.x + i * 256;
        x[i] = qr[idx] + pr[idx];
        ss += x[i] * x[i];
    }
    #pragma unroll
    for (int ofs = 16; ofs > 0; ofs >>= 1)
        ss += __shfl_xor_sync(0xffffffffu, ss, ofs);
    const int lane = threadIdx.x & 31, wid = threadIdx.x >> 5;
    if (lane == 0) sh[wid] = ss;
    __syncthreads();
    if (threadIdx.x == 0) {
        float tot = 0.f;
        #pragma unroll
        for (int i = 0; i < 8; i++) tot += sh[i];
        s_inv = rsqrtf(tot * (1.0f / D_) + RMS_EPS_);
    }
    __syncthreads();
    const float inv = s_inv;
    #pragma unroll
    for (int i = 0; i < 4; i++) {
        int idx = threadIdx.x + i * 256;
        orow[idx] = x[i] * inv * w[idx];
    }
}

// ---------------------------------------------------------------------------
extern "C" void kernel_launch(void* const* d_in, const int* in_sizes, int n_in,
                              void* d_out, int out_size)
{
    const float* query   = (const float*)d_in[0];
    const float* context = (const float*)d_in[1];
    const float* Wq      = (const float*)d_in[2];
    const float* Wk      = (const float*)d_in[3];
    const float* Wv      = (const float*)d_in[4];
    const float* Wo      = (const float*)d_in[5];
    const float* rmsw    = (const float*)d_in[6];
    float* out = (float*)d_out;

    float *pv, *pproj;
    cudaGetSymbolAddress((void**)&pv,    g_v);
    cudaGetSymbolAddress((void**)&pproj, g_proj);

    __nv_bfloat16 *qsh, *qsl, *csh, *csl, *ash, *asl;
    __nv_bfloat16 *wqh, *wql, *wkh, *wkl, *wvh, *wvl, *woh, *wol;
    __nv_bfloat16 *qe, *kke, *vte;
    cudaGetSymbolAddress((void**)&qsh, g_qsh);
    cudaGetSymbolAddress((void**)&qsl, g_qsl);
    cudaGetSymbolAddress((void**)&csh, g_csh);
    cudaGetSymbolAddress((void**)&csl, g_csl);
    cudaGetSymbolAddress((void**)&ash, g_ash);
    cudaGetSymbolAddress((void**)&asl, g_asl);
    cudaGetSymbolAddress((void**)&wqh, g_wqh);
    cudaGetSymbolAddress((void**)&wql, g_wql);
    cudaGetSymbolAddress((void**)&wkh, g_wkh);
    cudaGetSymbolAddress((void**)&wkl, g_wkl);
    cudaGetSymbolAddress((void**)&wvh, g_wvh);
    cudaGetSymbolAddress((void**)&wvl, g_wvl);
    cudaGetSymbolAddress((void**)&woh, g_woh);
    cudaGetSymbolAddress((void**)&wol, g_wol);
    cudaGetSymbolAddress((void**)&qe,  g_qe);
    cudaGetSymbolAddress((void**)&kke, g_ke);
    cudaGetSymbolAddress((void**)&vte, g_vte);

    cudaFuncSetAttribute(gemm_bf16_mma,
        cudaFuncAttributeMaxDynamicSharedMemorySize, GEMM_SMEM);
    cudaFuncSetAttribute(attn_mma,
        cudaFuncAttributeMaxDynamicSharedMemorySize, ATTN_SMEM);

    const int MQ = B_ * T_;   // 2048
    const int MK = B_ * S_;   // 4096

    // all input conversions in one launch
    split_all<<<10240, 256>>>(query, context, Wq, Wk, Wv, Wo);

    // projections — 128x128 tiles, hi/lo-split fragments
    dim3 gq(D_ / GTN, MQ / GTM);   // 8 x 16 = 128 CTAs
    dim3 gk(D_ / GTN, MK / GTM);   // 8 x 32 = 256 CTAs
    gemm_bf16_mma<<<gq, 256, GEMM_SMEM>>>(qsh, qsl, wqh, wql, nullptr, qe,  D_, 1, T_);
    gemm_bf16_mma<<<gk, 256, GEMM_SMEM>>>(csh, csl, wkh, wkl, nullptr, kke, D_, 2, S_);
    gemm_bf16_mma<<<gk, 256, GEMM_SMEM>>>(csh, csl, wvh, wvl, pv, nullptr,  D_, 0, 0);

    v_ext_t<<<dim3(S_ / 32, 2, B_ * H_), dim3(32, 8)>>>(pv, vte);

    // tensor-core attention
    attn_mma<<<dim3(T_ / AM, NS_, B_ * H_), 256, ATTN_SMEM>>>(qe, kke, vte);
    attn_combine_kernel<<<(B_ * H_ * T_) / 4, 256>>>(ash, asl);

    // output projection
    gemm_bf16_mma<<<gq, 256, GEMM_SMEM>>>(ash, asl, woh, wol, pproj, nullptr, D_, 0, 0);

    rms_kernel<<<MQ, 256>>>(query, pproj, rmsw, out);
}

// round 16
// speedup vs baseline: 1.7678x; 1.0699x over previous
#include <cuda_runtime.h>
#include <cuda_bf16.h>
#include <math.h>
#include <stdint.h>

// Problem constants
#define B_  2
#define T_  1024
#define S_  2048
#define D_  1024
#define H_  16
#define HD_ 64
#define SCALE_ 0.125f
#define RMS_EPS_ 1e-6f

#define NS_ 2
#define SPS (S_ / NS_)

// hi/lo split GEMM config
#define KD 1024
#define KB 32
#define NSTG (KD / KB)            // 32
#define GTM 128
#define GTN 128
#define GP2 80                    // smem row pitch bytes (64B data + 16 pad)
#define ASTG (GTM * GP2)          // 10240
#define STAGE (4 * ASTG)          // 40960
#define GEMM_SMEM (2 * STAGE)     // 81920

// attention mma config (hi/lo separate tiles, 64-dim rows)
#define AM 128
#define APC 144                   // pitch: 128B data + 16 pad
#define AQH 0
#define AQL (AM * APC)            // 18432
#define AKH (2 * AM * APC)        // 36864
#define AKL (AKH + 64 * APC)
#define AVH (AKL + 64 * APC)
#define AVL (AVH + 64 * APC)
#define ATTN_SMEM (AVL + 64 * APC)   // 73728

// Scratch (device globals; no allocation allowed)
__device__ float g_v[B_ * S_ * D_];
__device__ float g_proj[B_ * T_ * D_];
__device__ float g_pacc[NS_ * B_ * H_ * T_ * HD_];
__device__ float g_pm[NS_ * B_ * H_ * T_];
__device__ float g_pl[NS_ * B_ * H_ * T_];
// hi/lo split operands
__device__ __nv_bfloat16 g_qsh[(size_t)B_ * T_ * KD];
__device__ __nv_bfloat16 g_qsl[(size_t)B_ * T_ * KD];
__device__ __nv_bfloat16 g_csh[(size_t)B_ * S_ * KD];
__device__ __nv_bfloat16 g_csl[(size_t)B_ * S_ * KD];
__device__ __nv_bfloat16 g_ash[(size_t)B_ * T_ * KD];
__device__ __nv_bfloat16 g_asl[(size_t)B_ * T_ * KD];
__device__ __nv_bfloat16 g_wqh[(size_t)D_ * KD];
__device__ __nv_bfloat16 g_wql[(size_t)D_ * KD];
__device__ __nv_bfloat16 g_wkh[(size_t)D_ * KD];
__device__ __nv_bfloat16 g_wkl[(size_t)D_ * KD];
__device__ __nv_bfloat16 g_wvh[(size_t)D_ * KD];
__device__ __nv_bfloat16 g_wvl[(size_t)D_ * KD];
__device__ __nv_bfloat16 g_woh[(size_t)D_ * KD];
__device__ __nv_bfloat16 g_wol[(size_t)D_ * KD];
// attention operands: hi/lo per-head rows [bh][L][64]
__device__ __nv_bfloat16 g_qeh[(size_t)B_ * H_ * T_ * HD_];
__device__ __nv_bfloat16 g_qel[(size_t)B_ * H_ * T_ * HD_];
__device__ __nv_bfloat16 g_keh[(size_t)B_ * H_ * S_ * HD_];
__device__ __nv_bfloat16 g_kel[(size_t)B_ * H_ * S_ * HD_];
__device__ __nv_bfloat16 g_vte[(size_t)B_ * H_ * HD_ * 2 * S_];   // V^T [d][hi(S)|lo(S)]

// ============================ PTX helpers (base ISA) ========================
__device__ __forceinline__ uint32_t smem_u32(const void* p) {
    uint32_t a;
    asm("{ .reg .u64 t; cvta.to.shared.u64 t, %1; cvt.u32.u64 %0, t; }"
        : "=r"(a) : "l"(p));
    return a;
}

#define CP_ASYNC16(dst_u32, src_ptr) \
    asm volatile("cp.async.cg.shared.global [%0], [%1], 16;" \
        :: "r"(dst_u32), "l"(src_ptr))
#define CP_COMMIT() asm volatile("cp.async.commit_group;" ::: "memory")
#define CP_WAIT1()  asm volatile("cp.async.wait_group 1;" ::: "memory")
#define CP_WAIT0()  asm volatile("cp.async.wait_group 0;" ::: "memory")

#define LDMATRIX_X4(r0, r1, r2, r3, addr) \
    asm volatile("ldmatrix.sync.aligned.m8n8.x4.shared.b16 {%0,%1,%2,%3}, [%4];" \
        : "=r"(r0), "=r"(r1), "=r"(r2), "=r"(r3) : "r"(addr))

#define MMA16816(d0, d1, d2, d3, a0, a1, a2, a3, b0, b1) \
    asm volatile("mma.sync.aligned.m16n8k16.row.col.f32.bf16.bf16.f32 " \
        "{%0,%1,%2,%3}, {%4,%5,%6,%7}, {%8,%9}, {%0,%1,%2,%3};" \
        : "+f"(d0), "+f"(d1), "+f"(d2), "+f"(d3) \
        : "r"(a0), "r"(a1), "r"(a2), "r"(a3), "r"(b0), "r"(b1))

__device__ __forceinline__ uint32_t pack_bf16x2(float p0, float p1) {
    uint32_t d;
    asm("cvt.rn.bf16x2.f32 %0, %1, %2;" : "=r"(d) : "f"(p1), "f"(p0));
    return d;
}
__device__ __forceinline__ float bf16lo_f(uint32_t u) {
    return __uint_as_float(u << 16);
}
__device__ __forceinline__ float bf16hi_f(uint32_t u) {
    return __uint_as_float(u & 0xffff0000u);
}

// ---------------------------------------------------------------------------
// Mega split kernel (unchanged, validated).
// ---------------------------------------------------------------------------
__global__ __launch_bounds__(256) void split_all(
    const float* __restrict__ query, const float* __restrict__ context,
    const float* __restrict__ Wq, const float* __restrict__ Wk,
    const float* __restrict__ Wv, const float* __restrict__ Wo)
{
    const int bid = blockIdx.x;
    const float* in;
    __nv_bfloat16 *oh, *ol;
    if (bid < 2048) {
        in = query + (size_t)bid * D_;
        oh = g_qsh + (size_t)bid * KD;
        ol = g_qsl + (size_t)bid * KD;
    } else if (bid < 6144) {
        int r = bid - 2048;
        in = context + (size_t)r * D_;
        oh = g_csh + (size_t)r * KD;
        ol = g_csl + (size_t)r * KD;
    } else {
        int idx = bid - 6144;
        int w = idx >> 10;
        int r = idx & 1023;
        const float* Ws[4] = {Wq, Wk, Wv, Wo};
        __nv_bfloat16* Hs[4] = {g_wqh, g_wkh, g_wvh, g_woh};
        __nv_bfloat16* Ls[4] = {g_wql, g_wkl, g_wvl, g_wol};
        in = Ws[w] + (size_t)r * D_;
        oh = Hs[w] + (size_t)r * KD;
        ol = Ls[w] + (size_t)r * KD;
    }
    #pragma unroll
    for (int i = 0; i < 4; i++) {
        int c = threadIdx.x + i * 256;
        float x = in[c];
        __nv_bfloat16 hi = __float2bfloat16(x);
        __nv_bfloat16 lo = __float2bfloat16(x - __bfloat162float(hi));
        oh[c] = hi;
        ol[c] = lo;
    }
}

// v_ext_t (unchanged, validated)
__global__ __launch_bounds__(256) void v_ext_t(
    const float* __restrict__ v, __nv_bfloat16* __restrict__ out)
{
    __shared__ float tile[32][33];
    const int s0 = blockIdx.x * 32;
    const int d0 = blockIdx.y * 32;
    const int bh = blockIdx.z;
    const int b = bh / H_;
    const int h = bh % H_;
    const int tx = threadIdx.x, ty = threadIdx.y;
    #pragma unroll
    for (int i = 0; i < 4; i++) {
        int s = s0 + ty + i * 8;
        tile[ty + i * 8][tx] = v[((size_t)(b * S_ + s)) * D_ + h * 64 + d0 + tx];
    }
    __syncthreads();
    #pragma unroll
    for (int i = 0; i < 4; i++) {
        int d = d0 + ty + i * 8;
        float x = tile[tx][ty + i * 8];
        __nv_bfloat16 hi = __float2bfloat16(x);
        __nv_bfloat16 lo = __float2bfloat16(x - __bfloat162float(hi));
        __nv_bfloat16* orow = out + ((size_t)(bh * 64 + d)) * (2 * S_);
        orow[s0 + tx] = hi;
        orow[S_ + s0 + tx] = lo;
    }
}

// ---------------------------------------------------------------------------
// hi/lo-split bf16 mma.sync GEMM (validated R15 structure).
// emode 0: C fp32. emode!=0: per-head hi/lo ext rows (Eh, El).
// ---------------------------------------------------------------------------
__global__ __launch_bounds__(256, 2) void gemm_bf16_mma(
    const __nv_bfloat16* __restrict__ Ah, const __nv_bfloat16* __restrict__ Al,
    const __nv_bfloat16* __restrict__ Wh, const __nv_bfloat16* __restrict__ Wl,
    float* __restrict__ C,
    __nv_bfloat16* __restrict__ Eh, __nv_bfloat16* __restrict__ El,
    int N, int emode, int Lrows)
{
    extern __shared__ char gsm[];
    const uint32_t smb = smem_u32(gsm);

    const int tid = threadIdx.x;
    const int wid = tid >> 5;
    const int lane = tid & 31;
    const int wm = wid & 3;
    const int wn = wid >> 2;
    const int bm = blockIdx.y * GTM;
    const int bn = blockIdx.x * GTN;

    const int lrow = tid >> 1;
    const int lsub = tid & 1;
    const size_t arow = (size_t)(bm + lrow) * KD + lsub * 16;
    const size_t wrow = (size_t)(bn + lrow) * KD + lsub * 16;
    const __nv_bfloat16* gAh = Ah + arow;
    const __nv_bfloat16* gAl = Al + arow;
    const __nv_bfloat16* gWh = Wh + wrow;
    const __nv_bfloat16* gWl = Wl + wrow;
    const uint32_t lsm = lrow * GP2 + lsub * 32;

    float acc[2][8][4];
    #pragma unroll
    for (int mb = 0; mb < 2; mb++)
        #pragma unroll
        for (int nb = 0; nb < 8; nb++)
            #pragma unroll
            for (int i = 0; i < 4; i++) acc[mb][nb][i] = 0.f;

    const uint32_t a_row = wm * 32 + (lane & 15);
    const uint32_t a_koff = (lane >> 4) * 16;
    const uint32_t b_row = wn * 64 + (lane & 7) + 8 * ((lane >> 4) & 1);
    const uint32_t b_koff = ((lane >> 3) & 1) * 16;

    #pragma unroll
    for (int st = 0; st < 2; st++) {
        const uint32_t sb = smb + st * STAGE;
        #pragma unroll
        for (int j = 0; j < 2; j++) {
            CP_ASYNC16(sb + 0 * ASTG + lsm + j * 16, gAh + st * KB + j * 8);
            CP_ASYNC16(sb + 1 * ASTG + lsm + j * 16, gAl + st * KB + j * 8);
            CP_ASYNC16(sb + 2 * ASTG + lsm + j * 16, gWh + st * KB + j * 8);
            CP_ASYNC16(sb + 3 * ASTG + lsm + j * 16, gWl + st * KB + j * 8);
        }
        CP_COMMIT();
    }

    for (int c = 0; c < NSTG; c++) {
        const int buf = c & 1;
        CP_WAIT1();
        __syncthreads();

        const uint32_t sb = smb + buf * STAGE;
        const uint32_t bAh = sb + 0 * ASTG;
        const uint32_t bAl = sb + 1 * ASTG;
        const uint32_t bWh = sb + 2 * ASTG;
        const uint32_t bWl = sb + 3 * ASTG;

        #pragma unroll
        for (int kk = 0; kk < 2; kk++) {
            uint32_t ah[2][4], al[2][4], wf[8][2];
            #pragma unroll
            for (int mb = 0; mb < 2; mb++) {
                uint32_t ro = (a_row + mb * 16) * GP2 + kk * 32 + a_koff;
                LDMATRIX_X4(ah[mb][0], ah[mb][1], ah[mb][2], ah[mb][3], bAh + ro);
                LDMATRIX_X4(al[mb][0], al[mb][1], al[mb][2], al[mb][3], bAl + ro);
            }
            #pragma unroll
            for (int nb2 = 0; nb2 < 4; nb2++) {
                uint32_t ro = (b_row + nb2 * 16) * GP2 + kk * 32 + b_koff;
                LDMATRIX_X4(wf[nb2 * 2][0], wf[nb2 * 2][1],
                            wf[nb2 * 2 + 1][0], wf[nb2 * 2 + 1][1], bWh + ro);
            }
            #pragma unroll
            for (int mb = 0; mb < 2; mb++)
                #pragma unroll
                for (int nb = 0; nb < 8; nb++)
                    MMA16816(acc[mb][nb][0], acc[mb][nb][1],
                             acc[mb][nb][2], acc[mb][nb][3],
                             ah[mb][0], ah[mb][1], ah[mb][2], ah[mb][3],
                             wf[nb][0], wf[nb][1]);
            #pragma unroll
            for (int mb = 0; mb < 2; mb++)
                #pragma unroll
                for (int nb = 0; nb < 8; nb++)
                    MMA16816(acc[mb][nb][0], acc[mb][nb][1],
                             acc[mb][nb][2], acc[mb][nb][3],
                             al[mb][0], al[mb][1], al[mb][2], al[mb][3],
                             wf[nb][0], wf[nb][1]);
            #pragma unroll
            for (int nb2 = 0; nb2 < 4; nb2++) {
                uint32_t ro = (b_row + nb2 * 16) * GP2 + kk * 32 + b_koff;
                LDMATRIX_X4(wf[nb2 * 2][0], wf[nb2 * 2][1],
                            wf[nb2 * 2 + 1][0], wf[nb2 * 2 + 1][1], bWl + ro);
            }
            #pragma unroll
            for (int mb = 0; mb < 2; mb++)
                #pragma unroll
                for (int nb = 0; nb < 8; nb++)
                    MMA16816(acc[mb][nb][0], acc[mb][nb][1],
                             acc[mb][nb][2], acc[mb][nb][3],
                             ah[mb][0], ah[mb][1], ah[mb][2], ah[mb][3],
                             wf[nb][0], wf[nb][1]);
        }

        __syncthreads();
        if (c + 2 < NSTG) {
            const uint32_t pb = smb + buf * STAGE;
            #pragma unroll
            for (int j = 0; j < 2; j++) {
                CP_ASYNC16(pb + 0 * ASTG + lsm + j * 16, gAh + (c + 2) * KB + j * 8);
                CP_ASYNC16(pb + 1 * ASTG + lsm + j * 16, gAl + (c + 2) * KB + j * 8);
                CP_ASYNC16(pb + 2 * ASTG + lsm + j * 16, gWh + (c + 2) * KB + j * 8);
                CP_ASYNC16(pb + 3 * ASTG + lsm + j * 16, gWl + (c + 2) * KB + j * 8);
            }
        }
        CP_COMMIT();
    }
    CP_WAIT0();

    const int gr = lane >> 2;
    const int gc = (lane & 3) * 2;

    if (emode == 0) {
        #pragma unroll
        for (int mb = 0; mb < 2; mb++) {
            const int row0 = bm + wm * 32 + mb * 16 + gr;
            #pragma unroll
            for (int nb = 0; nb < 8; nb++) {
                const int col = bn + wn * 64 + nb * 8 + gc;
                *(float2*)&C[(size_t)row0 * N + col] =
                    make_float2(acc[mb][nb][0], acc[mb][nb][1]);
                *(float2*)&C[(size_t)(row0 + 8) * N + col] =
                    make_float2(acc[mb][nb][2], acc[mb][nb][3]);
            }
        }
    } else {
        #pragma unroll
        for (int mb = 0; mb < 2; mb++) {
            #pragma unroll
            for (int half = 0; half < 2; half++) {
                const int row = bm + wm * 32 + mb * 16 + gr + half * 8;
                const int b = row / Lrows;
                const int t = row % Lrows;
                #pragma unroll
                for (int nb = 0; nb < 8; nb++) {
                    const int col = bn + wn * 64 + nb * 8 + gc;
                    const int h = col >> 6;
                    const int dd = col & 63;
                    float x0 = acc[mb][nb][half * 2];
                    float x1 = acc[mb][nb][half * 2 + 1];
                    __nv_bfloat16 h0 = __float2bfloat16(x0);
                    __nv_bfloat16 h1 = __float2bfloat16(x1);
                    __nv_bfloat16 l0 = __float2bfloat16(x0 - __bfloat162float(h0));
                    __nv_bfloat16 l1 = __float2bfloat16(x1 - __bfloat162float(h1));
                    const size_t ro = ((size_t)(b * H_ + h) * Lrows + t) * HD_ + dd;
                    __nv_bfloat162 hv; hv.x = h0; hv.y = h1;
                    __nv_bfloat162 lv; lv.x = l0; lv.y = l1;
                    *(__nv_bfloat162*)&Eh[ro] = hv;
                    *(__nv_bfloat162*)&El[ro] = lv;
                }
            }
        }
    }
}

// ---------------------------------------------------------------------------
// Tensor-core flash attention, hi/lo shared fragments.
// CTA: 256 threads (8 warps x 16 query rows), S-tiles of 64.
// QK: 4 kk x {qh,ql LDSM; Khi 4; Klo 4} -> 24 MMA.  PV analogous via Vhi/Vlo.
// ---------------------------------------------------------------------------
__global__ __launch_bounds__(256) void attn_mma(
    const __nv_bfloat16* __restrict__ qeh, const __nv_bfloat16* __restrict__ qel,
    const __nv_bfloat16* __restrict__ keh, const __nv_bfloat16* __restrict__ kel,
    const __nv_bfloat16* __restrict__ vte)
{
    extern __shared__ char smraw[];
    const uint32_t smb = smem_u32(smraw);

    const int tid = threadIdx.x;
    const int wid = tid >> 5;
    const int lane = tid & 31;
    const int hb = blockIdx.z;
    const int split = blockIdx.y;
    const int t0 = blockIdx.x * AM;
    const int h = hb % H_;

    const float slope = exp2f(-(float)(h + 1) / 16.0f);
    const size_t qrow0 = (size_t)hb * T_ + t0;
    const size_t krow0 = (size_t)hb * S_;
    const size_t vrow0 = (size_t)hb * 64;

    // Q hi/lo tiles (128 rows x 64)
    for (int idx = tid; idx < AM * 8; idx += 256) {
        int r = idx >> 3, c = idx & 7;
        CP_ASYNC16(smb + AQH + r * APC + c * 16, qeh + (qrow0 + r) * HD_ + c * 8);
        CP_ASYNC16(smb + AQL + r * APC + c * 16, qel + (qrow0 + r) * HD_ + c * 8);
    }
    CP_COMMIT();

    float sc[8][4], oF[8][4];
    #pragma unroll
    for (int nb = 0; nb < 8; nb++)
        #pragma unroll
        for (int i = 0; i < 4; i++) oF[nb][i] = 0.f;
    float m0 = -INFINITY, m1 = -INFINITY, l0 = 0.f, l1 = 0.f;

    const int r0 = lane >> 2;
    const float trow0 = (float)(t0 + wid * 16 + r0);
    const float trow1 = trow0 + 8.0f;

    const uint32_t a_ro = (wid * 16 + (lane & 15)) * APC + (lane >> 4) * 16;
    const uint32_t b_row = (lane & 7) + 8 * ((lane >> 4) & 1);
    const uint32_t b_koff = ((lane >> 3) & 1) * 16;

    const int sbeg = split * SPS;
    const int send = sbeg + SPS;

    for (int s0 = sbeg; s0 < send; s0 += 64) {
        // K hi/lo and V hi/lo tiles (64 rows x 64 each)
        for (int idx = tid; idx < 64 * 8; idx += 256) {
            int r = idx >> 3, c = idx & 7;
            CP_ASYNC16(smb + AKH + r * APC + c * 16, keh + (krow0 + s0 + r) * HD_ + c * 8);
            CP_ASYNC16(smb + AKL + r * APC + c * 16, kel + (krow0 + s0 + r) * HD_ + c * 8);
            const __nv_bfloat16* vb = vte + (vrow0 + r) * (size_t)(2 * S_);
            CP_ASYNC16(smb + AVH + r * APC + c * 16, vb + s0 + c * 8);
            CP_ASYNC16(smb + AVL + r * APC + c * 16, vb + S_ + s0 + c * 8);
        }
        CP_COMMIT();
        CP_WAIT0();
        __syncthreads();

        // ----- QK: sc = Qh·Kh + Ql·Kh + Qh·Kl -----
        #pragma unroll
        for (int nb = 0; nb < 8; nb++)
            #pragma unroll
            for (int i = 0; i < 4; i++) sc[nb][i] = 0.f;

        #pragma unroll
        for (int kk = 0; kk < 4; kk++) {
            uint32_t qh[4], ql[4], kf[8][2];
            LDMATRIX_X4(qh[0], qh[1], qh[2], qh[3], smb + AQH + a_ro + kk * 32);
            LDMATRIX_X4(ql[0], ql[1], ql[2], ql[3], smb + AQL + a_ro + kk * 32);
            #pragma unroll
            for (int nb2 = 0; nb2 < 4; nb2++) {
                uint32_t ro = (b_row + nb2 * 16) * APC + kk * 32 + b_koff;
                LDMATRIX_X4(kf[nb2 * 2][0], kf[nb2 * 2][1],
                            kf[nb2 * 2 + 1][0], kf[nb2 * 2 + 1][1], smb + AKH + ro);
            }
            #pragma unroll
            for (int nb = 0; nb < 8; nb++)
                MMA16816(sc[nb][0], sc[nb][1], sc[nb][2], sc[nb][3],
                         qh[0], qh[1], qh[2], qh[3], kf[nb][0], kf[nb][1]);
            #pragma unroll
            for (int nb = 0; nb < 8; nb++)
                MMA16816(sc[nb][0], sc[nb][1], sc[nb][2], sc[nb][3],
                         ql[0], ql[1], ql[2], ql[3], kf[nb][0], kf[nb][1]);
            #pragma unroll
            for (int nb2 = 0; nb2 < 4; nb2++) {
                uint32_t ro = (b_row + nb2 * 16) * APC + kk * 32 + b_koff;
                LDMATRIX_X4(kf[nb2 * 2][0], kf[nb2 * 2][1],
                            kf[nb2 * 2 + 1][0], kf[nb2 * 2 + 1][1], smb + AKL + ro);
            }
            #pragma unroll
            for (int nb = 0; nb < 8; nb++)
                MMA16816(sc[nb][0], sc[nb][1], sc[nb][2], sc[nb][3],
                         qh[0], qh[1], qh[2], qh[3], kf[nb][0], kf[nb][1]);
        }

        // ----- scale + ALiBi + online softmax -----
        float tm0 = -INFINITY, tm1 = -INFINITY;
        #pragma unroll
        for (int nb = 0; nb < 8; nb++) {
            float scol = (float)(s0 + nb * 8 + 2 * (lane & 3));
            sc[nb][0] = sc[nb][0] * SCALE_ - slope * fabsf(trow0 - scol);
            sc[nb][1] = sc[nb][1] * SCALE_ - slope * fabsf(trow0 - (scol + 1.f));
            sc[nb][2] = sc[nb][2] * SCALE_ - slope * fabsf(trow1 - scol);
            sc[nb][3] = sc[nb][3] * SCALE_ - slope * fabsf(trow1 - (scol + 1.f));
            tm0 = fmaxf(tm0, fmaxf(sc[nb][0], sc[nb][1]));
            tm1 = fmaxf(tm1, fmaxf(sc[nb][2], sc[nb][3]));
        }
        tm0 = fmaxf(tm0, __shfl_xor_sync(0xffffffffu, tm0, 1));
        tm0 = fmaxf(tm0, __shfl_xor_sync(0xffffffffu, tm0, 2));
        tm1 = fmaxf(tm1, __shfl_xor_sync(0xffffffffu, tm1, 1));
        tm1 = fmaxf(tm1, __shfl_xor_sync(0xffffffffu, tm1, 2));

        float mn0 = fmaxf(m0, tm0);
        float mn1 = fmaxf(m1, tm1);
        float cr0 = __expf(m0 - mn0);
        float cr1 = __expf(m1 - mn1);
        l0 *= cr0; l1 *= cr1;
        #pragma unroll
        for (int nb = 0; nb < 8; nb++) {
            oF[nb][0] *= cr0; oF[nb][1] *= cr0;
            oF[nb][2] *= cr1; oF[nb][3] *= cr1;
        }

        float rs0 = 0.f, rs1 = 0.f;
        #pragma unroll
        for (int nb = 0; nb < 8; nb++) {
            sc[nb][0] = __expf(sc[nb][0] - mn0);
            sc[nb][1] = __expf(sc[nb][1] - mn0);
            sc[nb][2] = __expf(sc[nb][2] - mn1);
            sc[nb][3] = __expf(sc[nb][3] - mn1);
            rs0 += sc[nb][0] + sc[nb][1];
            rs1 += sc[nb][2] + sc[nb][3];
        }
        rs0 += __shfl_xor_sync(0xffffffffu, rs0, 1);
        rs0 += __shfl_xor_sync(0xffffffffu, rs0, 2);
        rs1 += __shfl_xor_sync(0xffffffffu, rs1, 1);
        rs1 += __shfl_xor_sync(0xffffffffu, rs1, 2);
        l0 += rs0; l1 += rs1;
        m0 = mn0; m1 = mn1;

        // ----- pack phi A-fragments (C-frag -> A-frag reuse) -----
        uint32_t phi[4][4];
        #pragma unroll
        for (int ks = 0; ks < 4; ks++) {
            phi[ks][0] = pack_bf16x2(sc[2 * ks][0], sc[2 * ks][1]);
            phi[ks][1] = pack_bf16x2(sc[2 * ks][2], sc[2 * ks][3]);
            phi[ks][2] = pack_bf16x2(sc[2 * ks + 1][0], sc[2 * ks + 1][1]);
            phi[ks][3] = pack_bf16x2(sc[2 * ks + 1][2], sc[2 * ks + 1][3]);
        }

        // ----- PV: oF += Ph·Vh + Pl·Vh + Ph·Vl -----
        #pragma unroll
        for (int kk = 0; kk < 4; kk++) {
            uint32_t plo[4];
            #pragma unroll
            for (int j = 0; j < 4; j++) {
                const int nb = 2 * kk + (j >> 1);
                const int ci = (j & 1) * 2;
                float pe = sc[nb][ci]     - bf16lo_f(phi[kk][j]);
                float po = sc[nb][ci + 1] - bf16hi_f(phi[kk][j]);
                plo[j] = pack_bf16x2(pe, po);
            }
            uint32_t vf[8][2];
            #pragma unroll
            for (int nb2 = 0; nb2 < 4; nb2++) {
                uint32_t ro = (b_row + nb2 * 16) * APC + kk * 32 + b_koff;
                LDMATRIX_X4(vf[nb2 * 2][0], vf[nb2 * 2][1],
                            vf[nb2 * 2 + 1][0], vf[nb2 * 2 + 1][1], smb + AVH + ro);
            }
            #pragma unroll
            for (int nb = 0; nb < 8; nb++)
                MMA16816(oF[nb][0], oF[nb][1], oF[nb][2], oF[nb][3],
                         phi[kk][0], phi[kk][1], phi[kk][2], phi[kk][3],
                         vf[nb][0], vf[nb][1]);
            #pragma unroll
            for (int nb = 0; nb < 8; nb++)
                MMA16816(oF[nb][0], oF[nb][1], oF[nb][2], oF[nb][3],
                         plo[0], plo[1], plo[2], plo[3],
                         vf[nb][0], vf[nb][1]);
            #pragma unroll
            for (int nb2 = 0; nb2 < 4; nb2++) {
                uint32_t ro = (b_row + nb2 * 16) * APC + kk * 32 + b_koff;
                LDMATRIX_X4(vf[nb2 * 2][0], vf[nb2 * 2][1],
                            vf[nb2 * 2 + 1][0], vf[nb2 * 2 + 1][1], smb + AVL + ro);
            }
            #pragma unroll
            for (int nb = 0; nb < 8; nb++)
                MMA16816(oF[nb][0], oF[nb][1], oF[nb][2], oF[nb][3],
                         phi[kk][0], phi[kk][1], phi[kk][2], phi[kk][3],
                         vf[nb][0], vf[nb][1]);
        }
        __syncthreads();
    }

    // epilogue: write raw partials + m,l
    const size_t base = (size_t)(split * B_ * H_ + hb) * T_;
    const size_t pidx0 = base + t0 + wid * 16 + r0;
    const size_t pidx1 = pidx0 + 8;
    #pragma unroll
    for (int nb = 0; nb < 8; nb++) {
        const int col = nb * 8 + 2 * (lane & 3);
        *(float2*)&g_pacc[pidx0 * HD_ + col] = make_float2(oF[nb][0], oF[nb][1]);
        *(float2*)&g_pacc[pidx1 * HD_ + col] = make_float2(oF[nb][2], oF[nb][3]);
    }
    if ((lane & 3) == 0) {
        g_pm[pidx0] = m0; g_pl[pidx0] = l0;
        g_pm[pidx1] = m1; g_pl[pidx1] = l1;
    }
}

// ---------------------------------------------------------------------------
// Combine split-KV partials -> hi/lo split rows (g_ash/g_asl)
// ---------------------------------------------------------------------------
__global__ __launch_bounds__(256) void attn_combine_kernel(
    __nv_bfloat16* __restrict__ ash, __nv_bfloat16* __restrict__ asl)
{
    const int d = threadIdx.x & 63;
    const int rlocal = threadIdx.x >> 6;
    const size_t row = (size_t)blockIdx.x * 4 + rlocal;
    const int t = row % T_;
    const int h = (row / T_) % H_;
    const int b = row / ((size_t)T_ * H_);

    float m0 = g_pm[row];
    float l0 = g_pl[row];
    float m1 = g_pm[(size_t)B_ * H_ * T_ + row];
    float l1 = g_pl[(size_t)B_ * H_ * T_ + row];

    float M = fmaxf(m0, m1);
    float e0 = __expf(m0 - M), e1 = __expf(m1 - M);
    float L = l0 * e0 + l1 * e1;
    float inv = 1.f / L;

    float a0 = g_pacc[row * HD_ + d];
    float a1 = g_pacc[((size_t)B_ * H_ * T_ + row) * HD_ + d];
    float val = (a0 * e0 + a1 * e1) * inv;

    __nv_bfloat16 hi = __float2bfloat16(val);
    __nv_bfloat16 lo = __float2bfloat16(val - __bfloat162float(hi));
    const int c = h * 64 + d;
    const size_t ro = (size_t)(b * T_ + t) * KD;
    ash[ro + c] = hi;
    asl[ro + c] = lo;
}

// ---------------------------------------------------------------------------
// residual + RMSNorm (unchanged)
// ---------------------------------------------------------------------------
__global__ __launch_bounds__(256) void rms_kernel(
    const float* __restrict__ query, const float* __restrict__ proj,
    const float* __restrict__ w, float* __restrict__ out)
{
    __shared__ float sh[8];
    __shared__ float s_inv;
    const size_t row = blockIdx.x;
    const float* qr = query + row * D_;
    const float* pr = proj + row * D_;
    float* orow = out + row * D_;

    float x[4];
    float ss = 0.f;
    #pragma unroll
    for (int i = 0; i < 4; i++) {
        int idx = threadIdx.x + i * 256;
        x[i] = qr[idx] + pr[idx];
        ss += x[i] * x[i];
    }
    #pragma unroll
    for (int ofs = 16; ofs > 0; ofs >>= 1)
        ss += __shfl_xor_sync(0xffffffffu, ss, ofs);
    const int lane = threadIdx.x & 31, wid = threadIdx.x >> 5;
    if (lane == 0) sh[wid] = ss;
    __syncthreads();
    if (threadIdx.x == 0) {
        float tot = 0.f;
        #pragma unroll
        for (int i = 0; i < 8; i++) tot += sh[i];
        s_inv = rsqrtf(tot * (1.0f / D_) + RMS_EPS_);
    }
    __syncthreads();
    const float inv = s_inv;
    #pragma unroll
    for (int i = 0; i < 4; i++) {
        int idx = threadIdx.x + i * 256;
        orow[idx] = x[i] * inv * w[idx];
    }
}

// ---------------------------------------------------------------------------
extern "C" void kernel_launch(void* const* d_in, const int* in_sizes, int n_in,
                              void* d_out, int out_size)
{
    const float* query   = (const float*)d_in[0];
    const float* context = (const float*)d_in[1];
    const float* Wq      = (const float*)d_in[2];
    const float* Wk      = (const float*)d_in[3];
    const float* Wv      = (const float*)d_in[4];
    const float* Wo      = (const float*)d_in[5];
    const float* rmsw    = (const float*)d_in[6];
    float* out = (float*)d_out;

    float *pv, *pproj;
    cudaGetSymbolAddress((void**)&pv,    g_v);
    cudaGetSymbolAddress((void**)&pproj, g_proj);

    __nv_bfloat16 *qsh, *qsl, *csh, *csl, *ash, *asl;
    __nv_bfloat16 *wqh, *wql, *wkh, *wkl, *wvh, *wvl, *woh, *wol;
    __nv_bfloat16 *qeh, *qel, *keh, *kel, *vte;
    cudaGetSymbolAddress((void**)&qsh, g_qsh);
    cudaGetSymbolAddress((void**)&qsl, g_qsl);
    cudaGetSymbolAddress((void**)&csh, g_csh);
    cudaGetSymbolAddress((void**)&csl, g_csl);
    cudaGetSymbolAddress((void**)&ash, g_ash);
    cudaGetSymbolAddress((void**)&asl, g_asl);
    cudaGetSymbolAddress((void**)&wqh, g_wqh);
    cudaGetSymbolAddress((void**)&wql, g_wql);
    cudaGetSymbolAddress((void**)&wkh, g_wkh);
    cudaGetSymbolAddress((void**)&wkl, g_wkl);
    cudaGetSymbolAddress((void**)&wvh, g_wvh);
    cudaGetSymbolAddress((void**)&wvl, g_wvl);
    cudaGetSymbolAddress((void**)&woh, g_woh);
    cudaGetSymbolAddress((void**)&wol, g_wol);
    cudaGetSymbolAddress((void**)&qeh, g_qeh);
    cudaGetSymbolAddress((void**)&qel, g_qel);
    cudaGetSymbolAddress((void**)&keh, g_keh);
    cudaGetSymbolAddress((void**)&kel, g_kel);
    cudaGetSymbolAddress((void**)&vte, g_vte);

    cudaFuncSetAttribute(gemm_bf16_mma,
        cudaFuncAttributeMaxDynamicSharedMemorySize, GEMM_SMEM);
    cudaFuncSetAttribute(attn_mma,
        cudaFuncAttributeMaxDynamicSharedMemorySize, ATTN_SMEM);

    const int MQ = B_ * T_;   // 2048
    const int MK = B_ * S_;   // 4096

    // all input conversions in one launch
    split_all<<<10240, 256>>>(query, context, Wq, Wk, Wv, Wo);

    // projections
    dim3 gq(D_ / GTN, MQ / GTM);
    dim3 gk(D_ / GTN, MK / GTM);
    gemm_bf16_mma<<<gq, 256, GEMM_SMEM>>>(qsh, qsl, wqh, wql, nullptr, qeh, qel, D_, 1, T_);
    gemm_bf16_mma<<<gk, 256, GEMM_SMEM>>>(csh, csl, wkh, wkl, nullptr, keh, kel, D_, 1, S_);
    gemm_bf16_mma<<<gk, 256, GEMM_SMEM>>>(csh, csl, wvh, wvl, pv, nullptr, nullptr, D_, 0, 0);

    v_ext_t<<<dim3(S_ / 32, 2, B_ * H_), dim3(32, 8)>>>(pv, vte);

    // tensor-core attention
    attn_mma<<<dim3(T_ / AM, NS_, B_ * H_), 256, ATTN_SMEM>>>(qeh, qel, keh, kel, vte);
    attn_combine_kernel<<<(B_ * H_ * T_) / 4, 256>>>(ash, asl);

    // output projection
    gemm_bf16_mma<<<gq, 256, GEMM_SMEM>>>(ash, asl, woh, wol, pproj, nullptr, nullptr, D_, 0, 0);

    rms_kernel<<<MQ, 256>>>(query, pproj, rmsw, out);
}

// round 17
// speedup vs baseline: 1.8069x; 1.0221x over previous
#include <cuda_runtime.h>
#include <cuda_bf16.h>
#include <math.h>
#include <stdint.h>

// Problem constants
#define B_  2
#define T_  1024
#define S_  2048
#define D_  1024
#define H_  16
#define HD_ 64
#define SCALE_ 0.125f
#define RMS_EPS_ 1e-6f

#define NS_ 2
#define SPS (S_ / NS_)

// hi/lo split GEMM config
#define KD 1024
#define KB 32
#define NSTG (KD / KB)            // 32
#define GTM 128
#define GTN 128
#define GP2 80                    // smem row pitch bytes (64B data + 16 pad)
#define ASTG (GTM * GP2)          // 10240
#define STAGE (4 * ASTG)          // 40960
#define GEMM_SMEM (2 * STAGE)     // 81920

// attention mma config (hi/lo tiles, double-buffered K/V)
#define AM 128
#define APC 144                   // pitch: 128B data + 16 pad
#define AQH 0
#define AQL (AM * APC)            // 18432
#define KVBASE (2 * AM * APC)     // 36864
#define KVSTG (4 * 64 * APC)      // 36864 (KH|KL|VH|VL)
#define AKH 0
#define AKL (64 * APC)
#define AVH (2 * 64 * APC)
#define AVL (3 * 64 * APC)
#define ATTN_SMEM (KVBASE + 2 * KVSTG)   // 110592 -> 2 CTAs/SM

// Scratch (device globals; no allocation allowed)
__device__ float g_v[B_ * S_ * D_];
__device__ float g_proj[B_ * T_ * D_];
__device__ float g_pacc[NS_ * B_ * H_ * T_ * HD_];
__device__ float g_pm[NS_ * B_ * H_ * T_];
__device__ float g_pl[NS_ * B_ * H_ * T_];
// hi/lo split operands
__device__ __nv_bfloat16 g_qsh[(size_t)B_ * T_ * KD];
__device__ __nv_bfloat16 g_qsl[(size_t)B_ * T_ * KD];
__device__ __nv_bfloat16 g_csh[(size_t)B_ * S_ * KD];
__device__ __nv_bfloat16 g_csl[(size_t)B_ * S_ * KD];
__device__ __nv_bfloat16 g_ash[(size_t)B_ * T_ * KD];
__device__ __nv_bfloat16 g_asl[(size_t)B_ * T_ * KD];
__device__ __nv_bfloat16 g_wqh[(size_t)D_ * KD];
__device__ __nv_bfloat16 g_wql[(size_t)D_ * KD];
__device__ __nv_bfloat16 g_wkh[(size_t)D_ * KD];
__device__ __nv_bfloat16 g_wkl[(size_t)D_ * KD];
__device__ __nv_bfloat16 g_wvh[(size_t)D_ * KD];
__device__ __nv_bfloat16 g_wvl[(size_t)D_ * KD];
__device__ __nv_bfloat16 g_woh[(size_t)D_ * KD];
__device__ __nv_bfloat16 g_wol[(size_t)D_ * KD];
// attention operands: hi/lo per-head rows [bh][L][64]
__device__ __nv_bfloat16 g_qeh[(size_t)B_ * H_ * T_ * HD_];
__device__ __nv_bfloat16 g_qel[(size_t)B_ * H_ * T_ * HD_];
__device__ __nv_bfloat16 g_keh[(size_t)B_ * H_ * S_ * HD_];
__device__ __nv_bfloat16 g_kel[(size_t)B_ * H_ * S_ * HD_];
__device__ __nv_bfloat16 g_vte[(size_t)B_ * H_ * HD_ * 2 * S_];   // V^T [d][hi(S)|lo(S)]

// ============================ PTX helpers (base ISA) ========================
__device__ __forceinline__ uint32_t smem_u32(const void* p) {
    uint32_t a;
    asm("{ .reg .u64 t; cvta.to.shared.u64 t, %1; cvt.u32.u64 %0, t; }"
        : "=r"(a) : "l"(p));
    return a;
}

#define CP_ASYNC16(dst_u32, src_ptr) \
    asm volatile("cp.async.cg.shared.global [%0], [%1], 16;" \
        :: "r"(dst_u32), "l"(src_ptr))
#define CP_COMMIT() asm volatile("cp.async.commit_group;" ::: "memory")
#define CP_WAIT1()  asm volatile("cp.async.wait_group 1;" ::: "memory")
#define CP_WAIT0()  asm volatile("cp.async.wait_group 0;" ::: "memory")

#define LDMATRIX_X4(r0, r1, r2, r3, addr) \
    asm volatile("ldmatrix.sync.aligned.m8n8.x4.shared.b16 {%0,%1,%2,%3}, [%4];" \
        : "=r"(r0), "=r"(r1), "=r"(r2), "=r"(r3) : "r"(addr))

#define MMA16816(d0, d1, d2, d3, a0, a1, a2, a3, b0, b1) \
    asm volatile("mma.sync.aligned.m16n8k16.row.col.f32.bf16.bf16.f32 " \
        "{%0,%1,%2,%3}, {%4,%5,%6,%7}, {%8,%9}, {%0,%1,%2,%3};" \
        : "+f"(d0), "+f"(d1), "+f"(d2), "+f"(d3) \
        : "r"(a0), "r"(a1), "r"(a2), "r"(a3), "r"(b0), "r"(b1))

__device__ __forceinline__ uint32_t pack_bf16x2(float p0, float p1) {
    uint32_t d;
    asm("cvt.rn.bf16x2.f32 %0, %1, %2;" : "=r"(d) : "f"(p1), "f"(p0));
    return d;
}
__device__ __forceinline__ float bf16lo_f(uint32_t u) {
    return __uint_as_float(u << 16);
}
__device__ __forceinline__ float bf16hi_f(uint32_t u) {
    return __uint_as_float(u & 0xffff0000u);
}

// ---------------------------------------------------------------------------
// Mega split kernel (unchanged, validated).
// ---------------------------------------------------------------------------
__global__ __launch_bounds__(256) void split_all(
    const float* __restrict__ query, const float* __restrict__ context,
    const float* __restrict__ Wq, const float* __restrict__ Wk,
    const float* __restrict__ Wv, const float* __restrict__ Wo)
{
    const int bid = blockIdx.x;
    const float* in;
    __nv_bfloat16 *oh, *ol;
    if (bid < 2048) {
        in = query + (size_t)bid * D_;
        oh = g_qsh + (size_t)bid * KD;
        ol = g_qsl + (size_t)bid * KD;
    } else if (bid < 6144) {
        int r = bid - 2048;
        in = context + (size_t)r * D_;
        oh = g_csh + (size_t)r * KD;
        ol = g_csl + (size_t)r * KD;
    } else {
        int idx = bid - 6144;
        int w = idx >> 10;
        int r = idx & 1023;
        const float* Ws[4] = {Wq, Wk, Wv, Wo};
        __nv_bfloat16* Hs[4] = {g_wqh, g_wkh, g_wvh, g_woh};
        __nv_bfloat16* Ls[4] = {g_wql, g_wkl, g_wvl, g_wol};
        in = Ws[w] + (size_t)r * D_;
        oh = Hs[w] + (size_t)r * KD;
        ol = Ls[w] + (size_t)r * KD;
    }
    #pragma unroll
    for (int i = 0; i < 4; i++) {
        int c = threadIdx.x + i * 256;
        float x = in[c];
        __nv_bfloat16 hi = __float2bfloat16(x);
        __nv_bfloat16 lo = __float2bfloat16(x - __bfloat162float(hi));
        oh[c] = hi;
        ol[c] = lo;
    }
}

// v_ext_t (unchanged, validated)
__global__ __launch_bounds__(256) void v_ext_t(
    const float* __restrict__ v, __nv_bfloat16* __restrict__ out)
{
    __shared__ float tile[32][33];
    const int s0 = blockIdx.x * 32;
    const int d0 = blockIdx.y * 32;
    const int bh = blockIdx.z;
    const int b = bh / H_;
    const int h = bh % H_;
    const int tx = threadIdx.x, ty = threadIdx.y;
    #pragma unroll
    for (int i = 0; i < 4; i++) {
        int s = s0 + ty + i * 8;
        tile[ty + i * 8][tx] = v[((size_t)(b * S_ + s)) * D_ + h * 64 + d0 + tx];
    }
    __syncthreads();
    #pragma unroll
    for (int i = 0; i < 4; i++) {
        int d = d0 + ty + i * 8;
        float x = tile[tx][ty + i * 8];
        __nv_bfloat16 hi = __float2bfloat16(x);
        __nv_bfloat16 lo = __float2bfloat16(x - __bfloat162float(hi));
        __nv_bfloat16* orow = out + ((size_t)(bh * 64 + d)) * (2 * S_);
        orow[s0 + tx] = hi;
        orow[S_ + s0 + tx] = lo;
    }
}

// ---------------------------------------------------------------------------
// hi/lo-split bf16 mma.sync GEMM (validated R15/R16 structure).
// emode 0: C fp32. emode!=0: per-head hi/lo ext rows (Eh, El).
// ---------------------------------------------------------------------------
__global__ __launch_bounds__(256, 2) void gemm_bf16_mma(
    const __nv_bfloat16* __restrict__ Ah, const __nv_bfloat16* __restrict__ Al,
    const __nv_bfloat16* __restrict__ Wh, const __nv_bfloat16* __restrict__ Wl,
    float* __restrict__ C,
    __nv_bfloat16* __restrict__ Eh, __nv_bfloat16* __restrict__ El,
    int N, int emode, int Lrows)
{
    extern __shared__ char gsm[];
    const uint32_t smb = smem_u32(gsm);

    const int tid = threadIdx.x;
    const int wid = tid >> 5;
    const int lane = tid & 31;
    const int wm = wid & 3;
    const int wn = wid >> 2;
    const int bm = blockIdx.y * GTM;
    const int bn = blockIdx.x * GTN;

    const int lrow = tid >> 1;
    const int lsub = tid & 1;
    const size_t arow = (size_t)(bm + lrow) * KD + lsub * 16;
    const size_t wrow = (size_t)(bn + lrow) * KD + lsub * 16;
    const __nv_bfloat16* gAh = Ah + arow;
    const __nv_bfloat16* gAl = Al + arow;
    const __nv_bfloat16* gWh = Wh + wrow;
    const __nv_bfloat16* gWl = Wl + wrow;
    const uint32_t lsm = lrow * GP2 + lsub * 32;

    float acc[2][8][4];
    #pragma unroll
    for (int mb = 0; mb < 2; mb++)
        #pragma unroll
        for (int nb = 0; nb < 8; nb++)
            #pragma unroll
            for (int i = 0; i < 4; i++) acc[mb][nb][i] = 0.f;

    const uint32_t a_row = wm * 32 + (lane & 15);
    const uint32_t a_koff = (lane >> 4) * 16;
    const uint32_t b_row = wn * 64 + (lane & 7) + 8 * ((lane >> 4) & 1);
    const uint32_t b_koff = ((lane >> 3) & 1) * 16;

    #pragma unroll
    for (int st = 0; st < 2; st++) {
        const uint32_t sb = smb + st * STAGE;
        #pragma unroll
        for (int j = 0; j < 2; j++) {
            CP_ASYNC16(sb + 0 * ASTG + lsm + j * 16, gAh + st * KB + j * 8);
            CP_ASYNC16(sb + 1 * ASTG + lsm + j * 16, gAl + st * KB + j * 8);
            CP_ASYNC16(sb + 2 * ASTG + lsm + j * 16, gWh + st * KB + j * 8);
            CP_ASYNC16(sb + 3 * ASTG + lsm + j * 16, gWl + st * KB + j * 8);
        }
        CP_COMMIT();
    }

    for (int c = 0; c < NSTG; c++) {
        const int buf = c & 1;
        CP_WAIT1();
        __syncthreads();

        const uint32_t sb = smb + buf * STAGE;
        const uint32_t bAh = sb + 0 * ASTG;
        const uint32_t bAl = sb + 1 * ASTG;
        const uint32_t bWh = sb + 2 * ASTG;
        const uint32_t bWl = sb + 3 * ASTG;

        #pragma unroll
        for (int kk = 0; kk < 2; kk++) {
            uint32_t ah[2][4], al[2][4], wf[8][2];
            #pragma unroll
            for (int mb = 0; mb < 2; mb++) {
                uint32_t ro = (a_row + mb * 16) * GP2 + kk * 32 + a_koff;
                LDMATRIX_X4(ah[mb][0], ah[mb][1], ah[mb][2], ah[mb][3], bAh + ro);
                LDMATRIX_X4(al[mb][0], al[mb][1], al[mb][2], al[mb][3], bAl + ro);
            }
            #pragma unroll
            for (int nb2 = 0; nb2 < 4; nb2++) {
                uint32_t ro = (b_row + nb2 * 16) * GP2 + kk * 32 + b_koff;
                LDMATRIX_X4(wf[nb2 * 2][0], wf[nb2 * 2][1],
                            wf[nb2 * 2 + 1][0], wf[nb2 * 2 + 1][1], bWh + ro);
            }
            #pragma unroll
            for (int mb = 0; mb < 2; mb++)
                #pragma unroll
                for (int nb = 0; nb < 8; nb++)
                    MMA16816(acc[mb][nb][0], acc[mb][nb][1],
                             acc[mb][nb][2], acc[mb][nb][3],
                             ah[mb][0], ah[mb][1], ah[mb][2], ah[mb][3],
                             wf[nb][0], wf[nb][1]);
            #pragma unroll
            for (int mb = 0; mb < 2; mb++)
                #pragma unroll
                for (int nb = 0; nb < 8; nb++)
                    MMA16816(acc[mb][nb][0], acc[mb][nb][1],
                             acc[mb][nb][2], acc[mb][nb][3],
                             al[mb][0], al[mb][1], al[mb][2], al[mb][3],
                             wf[nb][0], wf[nb][1]);
            #pragma unroll
            for (int nb2 = 0; nb2 < 4; nb2++) {
                uint32_t ro = (b_row + nb2 * 16) * GP2 + kk * 32 + b_koff;
                LDMATRIX_X4(wf[nb2 * 2][0], wf[nb2 * 2][1],
                            wf[nb2 * 2 + 1][0], wf[nb2 * 2 + 1][1], bWl + ro);
            }
            #pragma unroll
            for (int mb = 0; mb < 2; mb++)
                #pragma unroll
                for (int nb = 0; nb < 8; nb++)
                    MMA16816(acc[mb][nb][0], acc[mb][nb][1],
                             acc[mb][nb][2], acc[mb][nb][3],
                             ah[mb][0], ah[mb][1], ah[mb][2], ah[mb][3],
                             wf[nb][0], wf[nb][1]);
        }

        __syncthreads();
        if (c + 2 < NSTG) {
            const uint32_t pb = smb + buf * STAGE;
            #pragma unroll
            for (int j = 0; j < 2; j++) {
                CP_ASYNC16(pb + 0 * ASTG + lsm + j * 16, gAh + (c + 2) * KB + j * 8);
                CP_ASYNC16(pb + 1 * ASTG + lsm + j * 16, gAl + (c + 2) * KB + j * 8);
                CP_ASYNC16(pb + 2 * ASTG + lsm + j * 16, gWh + (c + 2) * KB + j * 8);
                CP_ASYNC16(pb + 3 * ASTG + lsm + j * 16, gWl + (c + 2) * KB + j * 8);
            }
        }
        CP_COMMIT();
    }
    CP_WAIT0();

    const int gr = lane >> 2;
    const int gc = (lane & 3) * 2;

    if (emode == 0) {
        #pragma unroll
        for (int mb = 0; mb < 2; mb++) {
            const int row0 = bm + wm * 32 + mb * 16 + gr;
            #pragma unroll
            for (int nb = 0; nb < 8; nb++) {
                const int col = bn + wn * 64 + nb * 8 + gc;
                *(float2*)&C[(size_t)row0 * N + col] =
                    make_float2(acc[mb][nb][0], acc[mb][nb][1]);
                *(float2*)&C[(size_t)(row0 + 8) * N + col] =
                    make_float2(acc[mb][nb][2], acc[mb][nb][3]);
            }
        }
    } else {
        #pragma unroll
        for (int mb = 0; mb < 2; mb++) {
            #pragma unroll
            for (int half = 0; half < 2; half++) {
                const int row = bm + wm * 32 + mb * 16 + gr + half * 8;
                const int b = row / Lrows;
                const int t = row % Lrows;
                #pragma unroll
                for (int nb = 0; nb < 8; nb++) {
                    const int col = bn + wn * 64 + nb * 8 + gc;
                    const int h = col >> 6;
                    const int dd = col & 63;
                    float x0 = acc[mb][nb][half * 2];
                    float x1 = acc[mb][nb][half * 2 + 1];
                    __nv_bfloat16 h0 = __float2bfloat16(x0);
                    __nv_bfloat16 h1 = __float2bfloat16(x1);
                    __nv_bfloat16 l0 = __float2bfloat16(x0 - __bfloat162float(h0));
                    __nv_bfloat16 l1 = __float2bfloat16(x1 - __bfloat162float(h1));
                    const size_t ro = ((size_t)(b * H_ + h) * Lrows + t) * HD_ + dd;
                    __nv_bfloat162 hv; hv.x = h0; hv.y = h1;
                    __nv_bfloat162 lv; lv.x = l0; lv.y = l1;
                    *(__nv_bfloat162*)&Eh[ro] = hv;
                    *(__nv_bfloat162*)&El[ro] = lv;
                }
            }
        }
    }
}

// ---------------------------------------------------------------------------
// Tensor-core flash attention, hi/lo shared fragments,
// DOUBLE-BUFFERED K/V tiles (2-stage cp.async ring), 2 CTAs/SM.
// ---------------------------------------------------------------------------
__global__ __launch_bounds__(256, 2) void attn_mma(
    const __nv_bfloat16* __restrict__ qeh, const __nv_bfloat16* __restrict__ qel,
    const __nv_bfloat16* __restrict__ keh, const __nv_bfloat16* __restrict__ kel,
    const __nv_bfloat16* __restrict__ vte)
{
    extern __shared__ char smraw[];
    const uint32_t smb = smem_u32(smraw);

    const int tid = threadIdx.x;
    const int wid = tid >> 5;
    const int lane = tid & 31;
    const int hb = blockIdx.z;
    const int split = blockIdx.y;
    const int t0 = blockIdx.x * AM;
    const int h = hb % H_;

    const float slope = exp2f(-(float)(h + 1) / 16.0f);
    const size_t qrow0 = (size_t)hb * T_ + t0;
    const size_t krow0 = (size_t)hb * S_;
    const size_t vrow0 = (size_t)hb * 64;

    const int sbeg = split * SPS;
    const int NT = SPS / 64;       // 16 tiles

    // group 0: Q hi/lo tiles (128 rows x 64)
    for (int idx = tid; idx < AM * 8; idx += 256) {
        int r = idx >> 3, c = idx & 7;
        CP_ASYNC16(smb + AQH + r * APC + c * 16, qeh + (qrow0 + r) * HD_ + c * 8);
        CP_ASYNC16(smb + AQL + r * APC + c * 16, qel + (qrow0 + r) * HD_ + c * 8);
    }
    CP_COMMIT();

    // tile loader helper (macro-free inline)
    // groups 1,2: tiles 0,1 into stages 0,1
    #pragma unroll
    for (int st = 0; st < 2; st++) {
        const int s0 = sbeg + st * 64;
        const uint32_t kb = smb + KVBASE + st * KVSTG;
        for (int idx = tid; idx < 64 * 8; idx += 256) {
            int r = idx >> 3, c = idx & 7;
            CP_ASYNC16(kb + AKH + r * APC + c * 16, keh + (krow0 + s0 + r) * HD_ + c * 8);
            CP_ASYNC16(kb + AKL + r * APC + c * 16, kel + (krow0 + s0 + r) * HD_ + c * 8);
            const __nv_bfloat16* vb = vte + (vrow0 + r) * (size_t)(2 * S_);
            CP_ASYNC16(kb + AVH + r * APC + c * 16, vb + s0 + c * 8);
            CP_ASYNC16(kb + AVL + r * APC + c * 16, vb + S_ + s0 + c * 8);
        }
        CP_COMMIT();
    }

    float sc[8][4], oF[8][4];
    #pragma unroll
    for (int nb = 0; nb < 8; nb++)
        #pragma unroll
        for (int i = 0; i < 4; i++) oF[nb][i] = 0.f;
    float m0 = -INFINITY, m1 = -INFINITY, l0 = 0.f, l1 = 0.f;

    const int r0 = lane >> 2;
    const float trow0 = (float)(t0 + wid * 16 + r0);
    const float trow1 = trow0 + 8.0f;

    const uint32_t a_ro = (wid * 16 + (lane & 15)) * APC + (lane >> 4) * 16;
    const uint32_t b_row = (lane & 7) + 8 * ((lane >> 4) & 1);
    const uint32_t b_koff = ((lane >> 3) & 1) * 16;

    for (int ct = 0; ct < NT; ct++) {
        const int s0 = sbeg + ct * 64;
        const uint32_t kb = smb + KVBASE + (ct & 1) * KVSTG;

        CP_WAIT1();           // tile ct complete; tile ct+1 in flight
        __syncthreads();

        // ----- QK: sc = Qh·Kh + Ql·Kh + Qh·Kl -----
        #pragma unroll
        for (int nb = 0; nb < 8; nb++)
            #pragma unroll
            for (int i = 0; i < 4; i++) sc[nb][i] = 0.f;

        #pragma unroll
        for (int kk = 0; kk < 4; kk++) {
            uint32_t qh[4], ql[4], kf[8][2];
            LDMATRIX_X4(qh[0], qh[1], qh[2], qh[3], smb + AQH + a_ro + kk * 32);
            LDMATRIX_X4(ql[0], ql[1], ql[2], ql[3], smb + AQL + a_ro + kk * 32);
            #pragma unroll
            for (int nb2 = 0; nb2 < 4; nb2++) {
                uint32_t ro = (b_row + nb2 * 16) * APC + kk * 32 + b_koff;
                LDMATRIX_X4(kf[nb2 * 2][0], kf[nb2 * 2][1],
                            kf[nb2 * 2 + 1][0], kf[nb2 * 2 + 1][1], kb + AKH + ro);
            }
            #pragma unroll
            for (int nb = 0; nb < 8; nb++)
                MMA16816(sc[nb][0], sc[nb][1], sc[nb][2], sc[nb][3],
                         qh[0], qh[1], qh[2], qh[3], kf[nb][0], kf[nb][1]);
            #pragma unroll
            for (int nb = 0; nb < 8; nb++)
                MMA16816(sc[nb][0], sc[nb][1], sc[nb][2], sc[nb][3],
                         ql[0], ql[1], ql[2], ql[3], kf[nb][0], kf[nb][1]);
            #pragma unroll
            for (int nb2 = 0; nb2 < 4; nb2++) {
                uint32_t ro = (b_row + nb2 * 16) * APC + kk * 32 + b_koff;
                LDMATRIX_X4(kf[nb2 * 2][0], kf[nb2 * 2][1],
                            kf[nb2 * 2 + 1][0], kf[nb2 * 2 + 1][1], kb + AKL + ro);
            }
            #pragma unroll
            for (int nb = 0; nb < 8; nb++)
                MMA16816(sc[nb][0], sc[nb][1], sc[nb][2], sc[nb][3],
                         qh[0], qh[1], qh[2], qh[3], kf[nb][0], kf[nb][1]);
        }

        // ----- scale + ALiBi + online softmax -----
        float tm0 = -INFINITY, tm1 = -INFINITY;
        #pragma unroll
        for (int nb = 0; nb < 8; nb++) {
            float scol = (float)(s0 + nb * 8 + 2 * (lane & 3));
            sc[nb][0] = sc[nb][0] * SCALE_ - slope * fabsf(trow0 - scol);
            sc[nb][1] = sc[nb][1] * SCALE_ - slope * fabsf(trow0 - (scol + 1.f));
            sc[nb][2] = sc[nb][2] * SCALE_ - slope * fabsf(trow1 - scol);
            sc[nb][3] = sc[nb][3] * SCALE_ - slope * fabsf(trow1 - (scol + 1.f));
            tm0 = fmaxf(tm0, fmaxf(sc[nb][0], sc[nb][1]));
            tm1 = fmaxf(tm1, fmaxf(sc[nb][2], sc[nb][3]));
        }
        tm0 = fmaxf(tm0, __shfl_xor_sync(0xffffffffu, tm0, 1));
        tm0 = fmaxf(tm0, __shfl_xor_sync(0xffffffffu, tm0, 2));
        tm1 = fmaxf(tm1, __shfl_xor_sync(0xffffffffu, tm1, 1));
        tm1 = fmaxf(tm1, __shfl_xor_sync(0xffffffffu, tm1, 2));

        float mn0 = fmaxf(m0, tm0);
        float mn1 = fmaxf(m1, tm1);
        float cr0 = __expf(m0 - mn0);
        float cr1 = __expf(m1 - mn1);
        l0 *= cr0; l1 *= cr1;
        #pragma unroll
        for (int nb = 0; nb < 8; nb++) {
            oF[nb][0] *= cr0; oF[nb][1] *= cr0;
            oF[nb][2] *= cr1; oF[nb][3] *= cr1;
        }

        float rs0 = 0.f, rs1 = 0.f;
        #pragma unroll
        for (int nb = 0; nb < 8; nb++) {
            sc[nb][0] = __expf(sc[nb][0] - mn0);
            sc[nb][1] = __expf(sc[nb][1] - mn0);
            sc[nb][2] = __expf(sc[nb][2] - mn1);
            sc[nb][3] = __expf(sc[nb][3] - mn1);
            rs0 += sc[nb][0] + sc[nb][1];
            rs1 += sc[nb][2] + sc[nb][3];
        }
        rs0 += __shfl_xor_sync(0xffffffffu, rs0, 1);
        rs0 += __shfl_xor_sync(0xffffffffu, rs0, 2);
        rs1 += __shfl_xor_sync(0xffffffffu, rs1, 1);
        rs1 += __shfl_xor_sync(0xffffffffu, rs1, 2);
        l0 += rs0; l1 += rs1;
        m0 = mn0; m1 = mn1;

        // ----- pack phi A-fragments (C-frag -> A-frag reuse) -----
        uint32_t phi[4][4];
        #pragma unroll
        for (int ks = 0; ks < 4; ks++) {
            phi[ks][0] = pack_bf16x2(sc[2 * ks][0], sc[2 * ks][1]);
            phi[ks][1] = pack_bf16x2(sc[2 * ks][2], sc[2 * ks][3]);
            phi[ks][2] = pack_bf16x2(sc[2 * ks + 1][0], sc[2 * ks + 1][1]);
            phi[ks][3] = pack_bf16x2(sc[2 * ks + 1][2], sc[2 * ks + 1][3]);
        }

        // ----- PV: oF += Ph·Vh + Pl·Vh + Ph·Vl -----
        #pragma unroll
        for (int kk = 0; kk < 4; kk++) {
            uint32_t plo[4];
            #pragma unroll
            for (int j = 0; j < 4; j++) {
                const int nb = 2 * kk + (j >> 1);
                const int ci = (j & 1) * 2;
                float pe = sc[nb][ci]     - bf16lo_f(phi[kk][j]);
                float po = sc[nb][ci + 1] - bf16hi_f(phi[kk][j]);
                plo[j] = pack_bf16x2(pe, po);
            }
            uint32_t vf[8][2];
            #pragma unroll
            for (int nb2 = 0; nb2 < 4; nb2++) {
                uint32_t ro = (b_row + nb2 * 16) * APC + kk * 32 + b_koff;
                LDMATRIX_X4(vf[nb2 * 2][0], vf[nb2 * 2][1],
                            vf[nb2 * 2 + 1][0], vf[nb2 * 2 + 1][1], kb + AVH + ro);
            }
            #pragma unroll
            for (int nb = 0; nb < 8; nb++)
                MMA16816(oF[nb][0], oF[nb][1], oF[nb][2], oF[nb][3],
                         phi[kk][0], phi[kk][1], phi[kk][2], phi[kk][3],
                         vf[nb][0], vf[nb][1]);
            #pragma unroll
            for (int nb = 0; nb < 8; nb++)
                MMA16816(oF[nb][0], oF[nb][1], oF[nb][2], oF[nb][3],
                         plo[0], plo[1], plo[2], plo[3],
                         vf[nb][0], vf[nb][1]);
            #pragma unroll
            for (int nb2 = 0; nb2 < 4; nb2++) {
                uint32_t ro = (b_row + nb2 * 16) * APC + kk * 32 + b_koff;
                LDMATRIX_X4(vf[nb2 * 2][0], vf[nb2 * 2][1],
                            vf[nb2 * 2 + 1][0], vf[nb2 * 2 + 1][1], kb + AVL + ro);
            }
            #pragma unroll
            for (int nb = 0; nb < 8; nb++)
                MMA16816(oF[nb][0], oF[nb][1], oF[nb][2], oF[nb][3],
                         phi[kk][0], phi[kk][1], phi[kk][2], phi[kk][3],
                         vf[nb][0], vf[nb][1]);
        }

        __syncthreads();      // done reading stage ct&1
        // refill this stage with tile ct+2
        if (ct + 2 < NT) {
            const int sn = sbeg + (ct + 2) * 64;
            for (int idx = tid; idx < 64 * 8; idx += 256) {
                int r = idx >> 3, c = idx & 7;
                CP_ASYNC16(kb + AKH + r * APC + c * 16, keh + (krow0 + sn + r) * HD_ + c * 8);
                CP_ASYNC16(kb + AKL + r * APC + c * 16, kel + (krow0 + sn + r) * HD_ + c * 8);
                const __nv_bfloat16* vb = vte + (vrow0 + r) * (size_t)(2 * S_);
                CP_ASYNC16(kb + AVH + r * APC + c * 16, vb + sn + c * 8);
                CP_ASYNC16(kb + AVL + r * APC + c * 16, vb + S_ + sn + c * 8);
            }
        }
        CP_COMMIT();          // exactly one group per iteration
    }
    CP_WAIT0();

    // epilogue: write raw partials + m,l
    const size_t base = (size_t)(split * B_ * H_ + hb) * T_;
    const size_t pidx0 = base + t0 + wid * 16 + r0;
    const size_t pidx1 = pidx0 + 8;
    #pragma unroll
    for (int nb = 0; nb < 8; nb++) {
        const int col = nb * 8 + 2 * (lane & 3);
        *(float2*)&g_pacc[pidx0 * HD_ + col] = make_float2(oF[nb][0], oF[nb][1]);
        *(float2*)&g_pacc[pidx1 * HD_ + col] = make_float2(oF[nb][2], oF[nb][3]);
    }
    if ((lane & 3) == 0) {
        g_pm[pidx0] = m0; g_pl[pidx0] = l0;
        g_pm[pidx1] = m1; g_pl[pidx1] = l1;
    }
}

// ---------------------------------------------------------------------------
// Combine split-KV partials -> hi/lo split rows (g_ash/g_asl)
// ---------------------------------------------------------------------------
__global__ __launch_bounds__(256) void attn_combine_kernel(
    __nv_bfloat16* __restrict__ ash, __nv_bfloat16* __restrict__ asl)
{
    const int d = threadIdx.x & 63;
    const int rlocal = threadIdx.x >> 6;
    const size_t row = (size_t)blockIdx.x * 4 + rlocal;
    const int t = row % T_;
    const int h = (row / T_) % H_;
    const int b = row / ((size_t)T_ * H_);

    float m0 = g_pm[row];
    float l0 = g_pl[row];
    float m1 = g_pm[(size_t)B_ * H_ * T_ + row];
    float l1 = g_pl[(size_t)B_ * H_ * T_ + row];

    float M = fmaxf(m0, m1);
    float e0 = __expf(m0 - M), e1 = __expf(m1 - M);
    float L = l0 * e0 + l1 * e1;
    float inv = 1.f / L;

    float a0 = g_pacc[row * HD_ + d];
    float a1 = g_pacc[((size_t)B_ * H_ * T_ + row) * HD_ + d];
    float val = (a0 * e0 + a1 * e1) * inv;

    __nv_bfloat16 hi = __float2bfloat16(val);
    __nv_bfloat16 lo = __float2bfloat16(val - __bfloat162float(hi));
    const int c = h * 64 + d;
    const size_t ro = (size_t)(b * T_ + t) * KD;
    ash[ro + c] = hi;
    asl[ro + c] = lo;
}

// ---------------------------------------------------------------------------
// residual + RMSNorm (unchanged)
// ---------------------------------------------------------------------------
__global__ __launch_bounds__(256) void rms_kernel(
    const float* __restrict__ query, const float* __restrict__ proj,
    const float* __restrict__ w, float* __restrict__ out)
{
    __shared__ float sh[8];
    __shared__ float s_inv;
    const size_t row = blockIdx.x;
    const float* qr = query + row * D_;
    const float* pr = proj + row * D_;
    float* orow = out + row * D_;

    float x[4];
    float ss = 0.f;
    #pragma unroll
    for (int i = 0; i < 4; i++) {
        int idx = threadIdx.x + i * 256;
        x[i] = qr[idx] + pr[idx];
        ss += x[i] * x[i];
    }
    #pragma unroll
    for (int ofs = 16; ofs > 0; ofs >>= 1)
        ss += __shfl_xor_sync(0xffffffffu, ss, ofs);
    const int lane = threadIdx.x & 31, wid = threadIdx.x >> 5;
    if (lane == 0) sh[wid] = ss;
    __syncthreads();
    if (threadIdx.x == 0) {
        float tot = 0.f;
        #pragma unroll
        for (int i = 0; i < 8; i++) tot += sh[i];
        s_inv = rsqrtf(tot * (1.0f / D_) + RMS_EPS_);
    }
    __syncthreads();
    const float inv = s_inv;
    #pragma unroll
    for (int i = 0; i < 4; i++) {
        int idx = threadIdx.x + i * 256;
        orow[idx] = x[i] * inv * w[idx];
    }
}

// ---------------------------------------------------------------------------
extern "C" void kernel_launch(void* const* d_in, const int* in_sizes, int n_in,
                              void* d_out, int out_size)
{
    const float* query   = (const float*)d_in[0];
    const float* context = (const float*)d_in[1];
    const float* Wq      = (const float*)d_in[2];
    const float* Wk      = (const float*)d_in[3];
    const float* Wv      = (const float*)d_in[4];
    const float* Wo      = (const float*)d_in[5];
    const float* rmsw    = (const float*)d_in[6];
    float* out = (float*)d_out;

    float *pv, *pproj;
    cudaGetSymbolAddress((void**)&pv,    g_v);
    cudaGetSymbolAddress((void**)&pproj, g_proj);

    __nv_bfloat16 *qsh, *qsl, *csh, *csl, *ash, *asl;
    __nv_bfloat16 *wqh, *wql, *wkh, *wkl, *wvh, *wvl, *woh, *wol;
    __nv_bfloat16 *qeh, *qel, *keh, *kel, *vte;
    cudaGetSymbolAddress((void**)&qsh, g_qsh);
    cudaGetSymbolAddress((void**)&qsl, g_qsl);
    cudaGetSymbolAddress((void**)&csh, g_csh);
    cudaGetSymbolAddress((void**)&csl, g_csl);
    cudaGetSymbolAddress((void**)&ash, g_ash);
    cudaGetSymbolAddress((void**)&asl, g_asl);
    cudaGetSymbolAddress((void**)&wqh, g_wqh);
    cudaGetSymbolAddress((void**)&wql, g_wql);
    cudaGetSymbolAddress((void**)&wkh, g_wkh);
    cudaGetSymbolAddress((void**)&wkl, g_wkl);
    cudaGetSymbolAddress((void**)&wvh, g_wvh);
    cudaGetSymbolAddress((void**)&wvl, g_wvl);
    cudaGetSymbolAddress((void**)&woh, g_woh);
    cudaGetSymbolAddress((void**)&wol, g_wol);
    cudaGetSymbolAddress((void**)&qeh, g_qeh);
    cudaGetSymbolAddress((void**)&qel, g_qel);
    cudaGetSymbolAddress((void**)&keh, g_keh);
    cudaGetSymbolAddress((void**)&kel, g_kel);
    cudaGetSymbolAddress((void**)&vte, g_vte);

    cudaFuncSetAttribute(gemm_bf16_mma,
        cudaFuncAttributeMaxDynamicSharedMemorySize, GEMM_SMEM);
    cudaFuncSetAttribute(attn_mma,
        cudaFuncAttributeMaxDynamicSharedMemorySize, ATTN_SMEM);

    const int MQ = B_ * T_;   // 2048
    const int MK = B_ * S_;   // 4096

    // all input conversions in one launch
    split_all<<<10240, 256>>>(query, context, Wq, Wk, Wv, Wo);

    // projections
    dim3 gq(D_ / GTN, MQ / GTM);
    dim3 gk(D_ / GTN, MK / GTM);
    gemm_bf16_mma<<<gq, 256, GEMM_SMEM>>>(qsh, qsl, wqh, wql, nullptr, qeh, qel, D_, 1, T_);
    gemm_bf16_mma<<<gk, 256, GEMM_SMEM>>>(csh, csl, wkh, wkl, nullptr, keh, kel, D_, 1, S_);
    gemm_bf16_mma<<<gk, 256, GEMM_SMEM>>>(csh, csl, wvh, wvl, pv, nullptr, nullptr, D_, 0, 0);

    v_ext_t<<<dim3(S_ / 32, 2, B_ * H_), dim3(32, 8)>>>(pv, vte);

    // tensor-core attention (double-buffered K/V)
    attn_mma<<<dim3(T_ / AM, NS_, B_ * H_), 256, ATTN_SMEM>>>(qeh, qel, keh, kel, vte);
    attn_combine_kernel<<<(B_ * H_ * T_) / 4, 256>>>(ash, asl);

    // output projection
    gemm_bf16_mma<<<gq, 256, GEMM_SMEM>>>(ash, asl, woh, wol, pproj, nullptr, nullptr, D_, 0, 0);

    rms_kernel<<<MQ, 256>>>(query, pproj, rmsw, out);
}